// round 12
// baseline (speedup 1.0000x reference)
#include <cuda_runtime.h>
#include <cuda_fp16.h>
#include <math.h>
#include <stdint.h>

#define BB   4
#define TT   2048
#define DD   1024
#define HH   16
#define HSV  64
#define FF   4096
#define BT   (BB*TT)
#define QLD  (3*DD)          // packed qkv row stride (halfs)

// ---------------- scratch (device globals; no runtime allocation) ----------
__device__ __half g_xn [BT*DD];
__device__ __half g_qkv[(size_t)BT*3*DD];
__device__ __half g_ctx[BT*DD];
__device__ float  g_x1 [BT*DD];
__device__ __half g_h  [(size_t)BT*FF];
__device__ __half g_w  [12*1024*1024];   // qkv' 3M | proj' 1M | w1' 4M | w2' 4M

// ---------------- small helpers --------------------------------------------
__device__ __forceinline__ uint32_t s2u(const void* p) {
    return (uint32_t)__cvta_generic_to_shared(p);
}
__device__ __forceinline__ uint32_t pkh2(float a, float b) {
    __half2 h = __floats2half2_rn(a, b);
    return *reinterpret_cast<uint32_t*>(&h);
}
__device__ __forceinline__ float ex2(float x) {
    float r;
    asm("ex2.approx.ftz.f32 %0, %1;" : "=f"(r) : "f"(x));
    return r;
}
__device__ __forceinline__ void mma_f16(float* c, const uint32_t* a, const uint32_t* b) {
    asm volatile(
        "mma.sync.aligned.m16n8k16.row.col.f32.f16.f16.f32 "
        "{%0,%1,%2,%3}, {%4,%5,%6,%7}, {%8,%9}, {%0,%1,%2,%3};"
        : "+f"(c[0]), "+f"(c[1]), "+f"(c[2]), "+f"(c[3])
        : "r"(a[0]), "r"(a[1]), "r"(a[2]), "r"(a[3]), "r"(b[0]), "r"(b[1]));
}
#define LDSM4(r0,r1,r2,r3,a) \
    asm volatile("ldmatrix.sync.aligned.m8n8.x4.shared.b16 {%0,%1,%2,%3}, [%4];" \
        : "=r"(r0),"=r"(r1),"=r"(r2),"=r"(r3) : "r"(a))
#define LDSM4T(r0,r1,r2,r3,a) \
    asm volatile("ldmatrix.sync.aligned.m8n8.x4.trans.shared.b16 {%0,%1,%2,%3}, [%4];" \
        : "=r"(r0),"=r"(r1),"=r"(r2),"=r"(r3) : "r"(a))
__device__ __forceinline__ void cpa(uint32_t dst, const void* src) {
    asm volatile("cp.async.cg.shared.global [%0], [%1], 16;"
                 :: "r"(dst), "l"(src) : "memory");
}
#define CP_COMMIT() asm volatile("cp.async.commit_group;" ::: "memory")
template<int N> __device__ __forceinline__ void cp_wait() {
    asm volatile("cp.async.wait_group %0;" :: "n"(N) : "memory");
}

// ---------------- weight repack kernels (fp32 -> fp16) ----------------------
__global__ void transpose_qkv3(const float* __restrict__ wq, const float* __restrict__ wk,
                               const float* __restrict__ wv, __half* __restrict__ out) {
    __shared__ float sm_[32][33];
    int z = blockIdx.z;
    int which = z >> 4, h = z & 15;
    const float* w = (which == 0) ? wq : (which == 1) ? wk : wv;
    __half* o = out + (size_t)which * DD * DD;
    int d0 = blockIdx.x * 32, j0 = blockIdx.y * 32;
    sm_[threadIdx.y][threadIdx.x] =
        w[((size_t)h * DD + d0 + threadIdx.y) * HSV + j0 + threadIdx.x];
    __syncthreads();
    o[(size_t)(h * HSV + j0 + threadIdx.y) * DD + d0 + threadIdx.x] =
        __float2half_rn(sm_[threadIdx.x][threadIdx.y]);
}
__global__ void transpose_rest(const float* __restrict__ wp, const float* __restrict__ w1,
                               const float* __restrict__ w2, __half* __restrict__ out) {
    __shared__ float sm_[32][33];
    int idx = blockIdx.x;
    const float* in; __half* o; int K, N, n0, k0;
    if (idx < 1024) {                        // proj: [1024,1024]
        in = wp; o = out + 3 * 1024 * 1024; K = 1024; N = 1024;
        n0 = (idx & 31) * 32; k0 = (idx >> 5) * 32;
    } else if (idx < 1024 + 4096) {          // w1: [1024,4096]
        int t = idx - 1024;
        in = w1; o = out + 4 * 1024 * 1024; K = 1024; N = 4096;
        n0 = (t & 127) * 32; k0 = (t >> 7) * 32;
    } else {                                 // w2: [4096,1024]
        int t = idx - 5120;
        in = w2; o = out + 8 * 1024 * 1024; K = 4096; N = 1024;
        n0 = (t & 31) * 32; k0 = (t >> 5) * 32;
    }
    sm_[threadIdx.y][threadIdx.x] = in[(size_t)(k0 + threadIdx.y) * N + n0 + threadIdx.x];
    __syncthreads();
    o[(size_t)(n0 + threadIdx.y) * K + k0 + threadIdx.x] =
        __float2half_rn(sm_[threadIdx.x][threadIdx.y]);
}

// ---------------- layernorm (fp32 in, fp16 out) -----------------------------
__global__ void ln_kernel(const float* __restrict__ x, const float* __restrict__ g,
                          const float* __restrict__ b, __half* __restrict__ out) {
    int row = blockIdx.x;
    const float* xr = x + (size_t)row * DD;
    float vv[4];
    float s = 0.f, sq = 0.f;
#pragma unroll
    for (int i = 0; i < 4; i++) {
        float t = xr[threadIdx.x + i * 256];
        vv[i] = t; s += t; sq += t * t;
    }
    __shared__ float red[64];
#pragma unroll
    for (int o = 16; o > 0; o >>= 1) {
        s  += __shfl_xor_sync(0xffffffffu, s, o);
        sq += __shfl_xor_sync(0xffffffffu, sq, o);
    }
    int warp = threadIdx.x >> 5, lane = threadIdx.x & 31;
    if (lane == 0) { red[warp] = s; red[warp + 8] = sq; }
    __syncthreads();
    if (threadIdx.x < 32) {
        float ss = (threadIdx.x < 8) ? red[threadIdx.x] : 0.f;
        float qq = (threadIdx.x < 8) ? red[threadIdx.x + 8] : 0.f;
#pragma unroll
        for (int o = 4; o > 0; o >>= 1) {
            ss += __shfl_xor_sync(0xffffffffu, ss, o);
            qq += __shfl_xor_sync(0xffffffffu, qq, o);
        }
        if (threadIdx.x == 0) { red[32] = ss; red[33] = qq; }
    }
    __syncthreads();
    float mean = red[32] * (1.f / DD);
    float var  = red[33] * (1.f / DD) - mean * mean;
    float inv  = rsqrtf(var + 1e-5f);
#pragma unroll
    for (int i = 0; i < 4; i++) {
        int c = threadIdx.x + i * 256;
        out[(size_t)row * DD + c] = __float2half_rn((vv[i] - mean) * inv * g[c] + b[c]);
    }
}

// ---------------- fp16 mma GEMM: C = A[MxK] @ Bt[NxK]^T ---------------------
// 256x128 CTA tile, BK=32, 3-stage cp.async, single sync/chunk
// (load-after-compute). 8 warps (4x2), warp tile 64x64. 1 CTA/SM.
// Per-SM operand traffic per chunk: 24KB (vs 40KB with 2x 128x128 CTAs).
#define GS 3
#define SPITCH 40                    // halfs per 32-col row (80B, LDSM-conflict-free)
#define STGH ((256+128)*SPITCH)      // halfs per stage (A+B)
#define ATILEH (256*SPITCH)

__device__ __forceinline__ void ld_stage(__half* sA, const __half* Ag, const __half* Bg,
                                         int K, int tid) {
#pragma unroll
    for (int i = 0; i < 4; i++) {                 // A: 256 rows x 4 16B-units
        int j = tid + (i << 8);
        int r = j >> 2, q = j & 3;
        cpa(s2u(sA + r * SPITCH + q * 8), Ag + (size_t)r * K + q * 8);
    }
    __half* sB = sA + ATILEH;
#pragma unroll
    for (int i = 0; i < 2; i++) {                 // B: 128 rows x 4 16B-units
        int j = tid + (i << 8);
        int r = j >> 2, q = j & 3;
        cpa(s2u(sB + r * SPITCH + q * 8), Bg + (size_t)r * K + q * 8);
    }
}

template<bool HOUT, bool BIAS, bool RELU, bool RES>
__global__ __launch_bounds__(256, 1)
void tc_gemm(const __half* __restrict__ A, const __half* __restrict__ Bt,
             const float* __restrict__ bias, const float* __restrict__ res,
             void* __restrict__ Cv, int M, int N, int K) {
    extern __shared__ __half sm[];
    int tid = threadIdx.x, wid = tid >> 5, lane = tid & 31;
    int wm = wid >> 1, wn = wid & 1;          // warp grid 4(M) x 2(N), 64x64 tiles
    int g = lane >> 2, tig = lane & 3;
    int n0 = blockIdx.x * 128, m0 = blockIdx.y * 256;

    const __half* Ab = A + (size_t)m0 * K;
    const __half* Bb = Bt + (size_t)n0 * K;
    int nch = K >> 5;

    float acc[4][8][4] = {};                  // i(16-row) x j(8-col) x frag

    // prologue: 2 chunks in flight
#pragma unroll
    for (int c = 0; c < GS - 1; c++) {
        ld_stage(sm + c * STGH, Ab + c * 32, Bb + c * 32, K, tid);
        CP_COMMIT();
    }

    for (int c = 0; c < nch; c++) {
        cp_wait<GS - 2>();          // chunk c's load complete
        __syncthreads();            // all warps done reading buffer (c-1)%GS
        __half* sA = sm + (c % GS) * STGH;
        __half* sB = sA + ATILEH;

        uint32_t bk[8][2][2];
#pragma unroll
        for (int j = 0; j < 8; j++) {
            uint32_t a = s2u(sB + (wn * 64 + j * 8 + (lane & 7)) * SPITCH
                             + ((lane >> 3) & 3) * 8);
            LDSM4(bk[j][0][0], bk[j][0][1], bk[j][1][0], bk[j][1][1], a);
        }
#pragma unroll
        for (int kk = 0; kk < 2; kk++) {
            uint32_t af[4][4];
#pragma unroll
            for (int i = 0; i < 4; i++) {
                uint32_t a = s2u(sA + (wm * 64 + i * 16 + (lane & 15)) * SPITCH
                                 + kk * 16 + (lane >> 4) * 8);
                LDSM4(af[i][0], af[i][1], af[i][2], af[i][3], a);
            }
#pragma unroll
            for (int i = 0; i < 4; i++)
#pragma unroll
                for (int j = 0; j < 8; j++)
                    mma_f16(acc[i][j], af[i], bk[j][kk]);
        }

        // issue next load AFTER compute; target buffer (c+2)%3 held chunk c-1,
        // whose reads finished before this iteration's barrier.
        if (c + GS - 1 < nch)
            ld_stage(sm + ((c + GS - 1) % GS) * STGH,
                     Ab + (size_t)(c + GS - 1) * 32,
                     Bb + (size_t)(c + GS - 1) * 32, K, tid);
        CP_COMMIT();
    }

    // epilogue
#pragma unroll
    for (int i = 0; i < 4; i++) {
        int m_up = m0 + wm * 64 + i * 16 + g;
#pragma unroll
        for (int j = 0; j < 8; j++) {
            int n = n0 + wn * 64 + j * 8 + 2 * tig;
            float v0 = acc[i][j][0], v1 = acc[i][j][1];
            float v2 = acc[i][j][2], v3 = acc[i][j][3];
            if (BIAS) {
                float2 bv = *(const float2*)(bias + n);
                v0 += bv.x; v1 += bv.y; v2 += bv.x; v3 += bv.y;
            }
            if (RELU) {
                v0 = fmaxf(v0, 0.f); v1 = fmaxf(v1, 0.f);
                v2 = fmaxf(v2, 0.f); v3 = fmaxf(v3, 0.f);
            }
            if (RES) {
                float2 r0 = *(const float2*)(res + (size_t)m_up * N + n);
                float2 r1 = *(const float2*)(res + (size_t)(m_up + 8) * N + n);
                v0 += r0.x; v1 += r0.y; v2 += r1.x; v3 += r1.y;
            }
            if (HOUT) {
                __half* C = (__half*)Cv;
                *(__half2*)(C + (size_t)m_up * N + n) = __floats2half2_rn(v0, v1);
                *(__half2*)(C + (size_t)(m_up + 8) * N + n) = __floats2half2_rn(v2, v3);
            } else {
                float* C = (float*)Cv;
                *(float2*)(C + (size_t)m_up * N + n) = make_float2(v0, v1);
                *(float2*)(C + (size_t)(m_up + 8) * N + n) = make_float2(v2, v3);
            }
        }
    }
}

// ---------------- fp16 mma causal flash attention ---------------------------
// Q tile 128 rows (8 warps x 16), K/V tiles 64 rows double-buffered.
// Heavy-first schedule: qt = gridDim.x-1-blockIdx.x.
#define APITCH 72
#define AQ_OFF 0
#define AK_OFF (128*APITCH)
#define AV_OFF (AK_OFF + 2*64*APITCH)
#define ASMEM_HALFS (AV_OFF + 2*64*APITCH)
#define SCL 0.18033688011112042f     // 0.125 * log2(e)

__device__ __forceinline__ void attn_ld_kv(__half* sm, int buf,
                                           const __half* kb, const __half* vb,
                                           int jt, int tid) {
    __half* Kd = sm + AK_OFF + buf * 64 * APITCH;
    __half* Vd = sm + AV_OFF + buf * 64 * APITCH;
#pragma unroll
    for (int i = 0; i < 2; i++) {
        int j = tid + (i << 8);
        int r = j >> 3, q = j & 7;
        size_t gr = (size_t)(jt * 64 + r) * QLD + q * 8;
        cpa(s2u(Kd + r * APITCH + q * 8), kb + gr);
        cpa(s2u(Vd + r * APITCH + q * 8), vb + gr);
    }
}

__global__ __launch_bounds__(256)
void attn_kernel(const __half* __restrict__ qkv, __half* __restrict__ ctx) {
    extern __shared__ __half smA[];
    __half* Qs = smA + AQ_OFF;

    int qt = (int)(gridDim.x - 1 - blockIdx.x);    // heavy tiles first
    int bh = blockIdx.y;
    int b = bh >> 4, h = bh & 15;
    int tid = threadIdx.x, w = tid >> 5, lane = tid & 31;
    int g = lane >> 2, t = lane & 3;

    const __half* qb = qkv + ((size_t)(b * TT) + qt * 128) * QLD + h * 64;
    const __half* kb = qkv + (size_t)(b * TT) * QLD + DD + h * 64;
    const __half* vb = kb + DD;

    // load Q tile (128 rows x 64 cols)
#pragma unroll
    for (int i = 0; i < 4; i++) {
        int j = tid + (i << 8);
        int r = j >> 3, q = j & 7;
        cpa(s2u(Qs + r * APITCH + q * 8), qb + (size_t)r * QLD + q * 8);
    }
    CP_COMMIT();
    cp_wait<0>();
    __syncthreads();

    uint32_t qf[4][4];
#pragma unroll
    for (int kk = 0; kk < 4; kk++) {
        uint32_t a = s2u(Qs + (w * 16 + (lane & 15)) * APITCH + kk * 16 + (lane >> 4) * 8);
        LDSM4(qf[kk][0], qf[kk][1], qf[kk][2], qf[kk][3], a);
    }

    float o[8][4] = {};
    float m0 = -1e30f, m1 = -1e30f, l0 = 0.f, l1 = 0.f;
    int row0 = qt * 128 + w * 16 + g, row1 = row0 + 8;
    int wmax = qt * 128 + w * 16 + 15;      // largest q-row in this warp
    int ntiles = 2 * qt + 2;

    attn_ld_kv(smA, 0, kb, vb, 0, tid);
    CP_COMMIT();

    for (int jt = 0; jt < ntiles; jt++) {
        cp_wait<0>();
        __syncthreads();
        int cur = jt & 1;
        if (jt + 1 < ntiles)
            attn_ld_kv(smA, (jt + 1) & 1, kb, vb, jt + 1, tid);
        CP_COMMIT();

        if (jt * 64 <= wmax) {
            __half* Ks = smA + AK_OFF + cur * 64 * APITCH;
            __half* Vs = smA + AV_OFF + cur * 64 * APITCH;

            // S = Q @ K^T
            float s[8][4] = {};
#pragma unroll
            for (int j = 0; j < 8; j++) {
                uint32_t bb[4][2];
                uint32_t a0 = s2u(Ks + (j * 8 + (lane & 7)) * APITCH + ((lane >> 3) & 3) * 8);
                LDSM4(bb[0][0], bb[0][1], bb[1][0], bb[1][1], a0);
                LDSM4(bb[2][0], bb[2][1], bb[3][0], bb[3][1], a0 + 64);
#pragma unroll
                for (int kk = 0; kk < 4; kk++) mma_f16(s[j], qf[kk], bb[kk]);
            }

            // scale (log2 domain) + causal mask
            bool anymask = (jt * 64 + 63 > row0);
#pragma unroll
            for (int j = 0; j < 8; j++) {
                s[j][0] *= SCL; s[j][1] *= SCL;
                s[j][2] *= SCL; s[j][3] *= SCL;
                if (anymask) {
                    int c0 = jt * 64 + j * 8 + 2 * t;
                    if (c0 > row0)     s[j][0] = -1e30f;
                    if (c0 + 1 > row0) s[j][1] = -1e30f;
                    if (c0 > row1)     s[j][2] = -1e30f;
                    if (c0 + 1 > row1) s[j][3] = -1e30f;
                }
            }

            // online softmax (log2 domain)
            float mx0 = -1e30f, mx1 = -1e30f;
#pragma unroll
            for (int j = 0; j < 8; j++) {
                mx0 = fmaxf(mx0, fmaxf(s[j][0], s[j][1]));
                mx1 = fmaxf(mx1, fmaxf(s[j][2], s[j][3]));
            }
            mx0 = fmaxf(mx0, __shfl_xor_sync(0xffffffffu, mx0, 1));
            mx0 = fmaxf(mx0, __shfl_xor_sync(0xffffffffu, mx0, 2));
            mx1 = fmaxf(mx1, __shfl_xor_sync(0xffffffffu, mx1, 1));
            mx1 = fmaxf(mx1, __shfl_xor_sync(0xffffffffu, mx1, 2));
            float mn0 = fmaxf(m0, mx0), mn1 = fmaxf(m1, mx1);
            float f0 = ex2(m0 - mn0), f1 = ex2(m1 - mn1);
            float sum0 = 0.f, sum1 = 0.f;
#pragma unroll
            for (int j = 0; j < 8; j++) {
                s[j][0] = ex2(s[j][0] - mn0);
                s[j][1] = ex2(s[j][1] - mn0);
                s[j][2] = ex2(s[j][2] - mn1);
                s[j][3] = ex2(s[j][3] - mn1);
                sum0 += s[j][0] + s[j][1];
                sum1 += s[j][2] + s[j][3];
            }
            sum0 += __shfl_xor_sync(0xffffffffu, sum0, 1);
            sum0 += __shfl_xor_sync(0xffffffffu, sum0, 2);
            sum1 += __shfl_xor_sync(0xffffffffu, sum1, 1);
            sum1 += __shfl_xor_sync(0xffffffffu, sum1, 2);
            l0 = l0 * f0 + sum0; l1 = l1 * f1 + sum1;
            m0 = mn0; m1 = mn1;
#pragma unroll
            for (int jo = 0; jo < 8; jo++) {
                o[jo][0] *= f0; o[jo][1] *= f0;
                o[jo][2] *= f1; o[jo][3] *= f1;
            }

            // O += P @ V
#pragma unroll
            for (int kk = 0; kk < 4; kk++) {
                uint32_t ap[4];
                ap[0] = pkh2(s[2*kk][0],   s[2*kk][1]);
                ap[1] = pkh2(s[2*kk][2],   s[2*kk][3]);
                ap[2] = pkh2(s[2*kk+1][0], s[2*kk+1][1]);
                ap[3] = pkh2(s[2*kk+1][2], s[2*kk+1][3]);
#pragma unroll
                for (int hb = 0; hb < 4; hb++) {
                    uint32_t bv[4];
                    uint32_t a = s2u(Vs + (kk * 16 + (lane & 15)) * APITCH
                                     + hb * 16 + (lane >> 4) * 8);
                    LDSM4T(bv[0], bv[1], bv[2], bv[3], a);
                    mma_f16(o[hb * 2],     ap, bv);
                    mma_f16(o[hb * 2 + 1], ap, bv + 2);
                }
            }
        }
    }

    float inv0 = 1.f / l0, inv1 = 1.f / l1;
    __half* c0 = ctx + ((size_t)(b * TT) + row0) * DD + h * 64;
    __half* c1 = ctx + ((size_t)(b * TT) + row1) * DD + h * 64;
#pragma unroll
    for (int jo = 0; jo < 8; jo++) {
        int col = jo * 8 + 2 * t;
        *(__half2*)(c0 + col) = __floats2half2_rn(o[jo][0] * inv0, o[jo][1] * inv0);
        *(__half2*)(c1 + col) = __floats2half2_rn(o[jo][2] * inv1, o[jo][3] * inv1);
    }
}

// ---------------- launcher --------------------------------------------------
extern "C" void kernel_launch(void* const* d_in, const int* in_sizes, int n_in,
                              void* d_out, int out_size) {
    const float* x      = (const float*)d_in[0];
    const float* ln1_g  = (const float*)d_in[1];
    const float* ln1_b  = (const float*)d_in[2];
    const float* wq     = (const float*)d_in[3];
    const float* wk     = (const float*)d_in[4];
    const float* wv     = (const float*)d_in[5];
    const float* w_proj = (const float*)d_in[6];
    const float* b_proj = (const float*)d_in[7];
    const float* ln2_g  = (const float*)d_in[8];
    const float* ln2_b  = (const float*)d_in[9];
    const float* w1     = (const float*)d_in[10];
    const float* b1     = (const float*)d_in[11];
    const float* w2     = (const float*)d_in[12];
    const float* b2     = (const float*)d_in[13];
    float* out = (float*)d_out;

    __half *xn, *qkv, *ctx, *hb, *w;
    float *x1;
    cudaGetSymbolAddress((void**)&xn,  g_xn);
    cudaGetSymbolAddress((void**)&qkv, g_qkv);
    cudaGetSymbolAddress((void**)&ctx, g_ctx);
    cudaGetSymbolAddress((void**)&x1,  g_x1);
    cudaGetSymbolAddress((void**)&hb,  g_h);
    cudaGetSymbolAddress((void**)&w,   g_w);
    __half* wqkv = w;                      // [3072, 1024]
    __half* wpro = w + 3 * 1024 * 1024;    // [1024, 1024]
    __half* w1t  = w + 4 * 1024 * 1024;    // [4096, 1024]
    __half* w2t  = w + 8 * 1024 * 1024;    // [1024, 4096]

    const size_t GSMEM = (size_t)GS * STGH * sizeof(__half);          // 92160
    const size_t ASMEM = (size_t)ASMEM_HALFS * sizeof(__half);        // 55296
    cudaFuncSetAttribute(tc_gemm<true ,false,false,false>, cudaFuncAttributeMaxDynamicSharedMemorySize, GSMEM);
    cudaFuncSetAttribute(tc_gemm<false,true ,false,true >, cudaFuncAttributeMaxDynamicSharedMemorySize, GSMEM);
    cudaFuncSetAttribute(tc_gemm<true ,true ,true ,false>, cudaFuncAttributeMaxDynamicSharedMemorySize, GSMEM);
    cudaFuncSetAttribute(attn_kernel, cudaFuncAttributeMaxDynamicSharedMemorySize, ASMEM);

    dim3 tb(32, 32);
    // (1) proj/w1/w2 repack (single launch; slot 4 = QKV GEMM for ncu)
    transpose_rest<<<9216, tb>>>(w_proj, w1, w2, w);
    // (2) qkv weight repack
    transpose_qkv3<<<dim3(32, 2, 48), tb>>>(wq, wk, wv, wqkv);
    // (3) LN1
    ln_kernel<<<BT, 256>>>(x, ln1_g, ln1_b, xn);
    // (4) fused QKV projection: [8192, 3072] fp16 out   (profiled slot)
    tc_gemm<true,false,false,false><<<dim3(24, 32), 256, GSMEM>>>(
        xn, wqkv, nullptr, nullptr, qkv, BT, 3 * DD, DD);
    // (5) attention (fp16 mma flash, 128-row Q tiles, heavy-first)
    attn_kernel<<<dim3(TT / 128, BB * HH), 256, ASMEM>>>(qkv, ctx);
    // (6) output projection + bias + residual -> x1 fp32
    tc_gemm<false,true,false,true><<<dim3(8, 32), 256, GSMEM>>>(
        ctx, wpro, b_proj, x, x1, BT, DD, DD);
    // (7) LN2
    ln_kernel<<<BT, 256>>>(x1, ln2_g, ln2_b, xn);
    // (8) FFN1: relu(xn @ w1 + b1) -> h fp16
    tc_gemm<true,true,true,false><<<dim3(32, 32), 256, GSMEM>>>(
        xn, w1t, b1, nullptr, hb, BT, FF, DD);
    // (9) FFN2: h @ w2 + b2 + x1 -> out fp32
    tc_gemm<false,true,false,true><<<dim3(8, 32), 256, GSMEM>>>(
        hb, w2t, b2, x1, out, BT, DD, FF);
}

// round 13
// speedup vs baseline: 1.1475x; 1.1475x over previous
#include <cuda_runtime.h>
#include <cuda_fp16.h>
#include <math.h>
#include <stdint.h>

#define BB   4
#define TT   2048
#define DD   1024
#define HH   16
#define HSV  64
#define FF   4096
#define BT   (BB*TT)
#define QLD  (3*DD)          // packed qkv row stride (halfs)

// ---------------- scratch (device globals; no runtime allocation) ----------
__device__ __half g_xn [BT*DD];
__device__ __half g_qkv[(size_t)BT*3*DD];
__device__ __half g_ctx[BT*DD];
__device__ float  g_x1 [BT*DD];
__device__ __half g_h  [(size_t)BT*FF];
__device__ __half g_w  [12*1024*1024];   // qkv' 3M | proj' 1M | w1' 4M | w2' 4M

// ---------------- small helpers --------------------------------------------
__device__ __forceinline__ uint32_t s2u(const void* p) {
    return (uint32_t)__cvta_generic_to_shared(p);
}
__device__ __forceinline__ uint32_t pkh2(float a, float b) {
    __half2 h = __floats2half2_rn(a, b);
    return *reinterpret_cast<uint32_t*>(&h);
}
__device__ __forceinline__ float ex2(float x) {
    float r;
    asm("ex2.approx.ftz.f32 %0, %1;" : "=f"(r) : "f"(x));
    return r;
}
__device__ __forceinline__ void mma_f16(float* c, const uint32_t* a, const uint32_t* b) {
    asm volatile(
        "mma.sync.aligned.m16n8k16.row.col.f32.f16.f16.f32 "
        "{%0,%1,%2,%3}, {%4,%5,%6,%7}, {%8,%9}, {%0,%1,%2,%3};"
        : "+f"(c[0]), "+f"(c[1]), "+f"(c[2]), "+f"(c[3])
        : "r"(a[0]), "r"(a[1]), "r"(a[2]), "r"(a[3]), "r"(b[0]), "r"(b[1]));
}
#define LDSM4(r0,r1,r2,r3,a) \
    asm volatile("ldmatrix.sync.aligned.m8n8.x4.shared.b16 {%0,%1,%2,%3}, [%4];" \
        : "=r"(r0),"=r"(r1),"=r"(r2),"=r"(r3) : "r"(a))
#define LDSM4T(r0,r1,r2,r3,a) \
    asm volatile("ldmatrix.sync.aligned.m8n8.x4.trans.shared.b16 {%0,%1,%2,%3}, [%4];" \
        : "=r"(r0),"=r"(r1),"=r"(r2),"=r"(r3) : "r"(a))
__device__ __forceinline__ void cpa(uint32_t dst, const void* src) {
    asm volatile("cp.async.cg.shared.global [%0], [%1], 16;"
                 :: "r"(dst), "l"(src) : "memory");
}
#define CP_COMMIT() asm volatile("cp.async.commit_group;" ::: "memory")
template<int N> __device__ __forceinline__ void cp_wait() {
    asm volatile("cp.async.wait_group %0;" :: "n"(N) : "memory");
}

// ---------------- weight repack kernels (fp32 -> fp16) ----------------------
__global__ void transpose_qkv3(const float* __restrict__ wq, const float* __restrict__ wk,
                               const float* __restrict__ wv, __half* __restrict__ out) {
    __shared__ float sm_[32][33];
    int z = blockIdx.z;
    int which = z >> 4, h = z & 15;
    const float* w = (which == 0) ? wq : (which == 1) ? wk : wv;
    __half* o = out + (size_t)which * DD * DD;
    int d0 = blockIdx.x * 32, j0 = blockIdx.y * 32;
    sm_[threadIdx.y][threadIdx.x] =
        w[((size_t)h * DD + d0 + threadIdx.y) * HSV + j0 + threadIdx.x];
    __syncthreads();
    o[(size_t)(h * HSV + j0 + threadIdx.y) * DD + d0 + threadIdx.x] =
        __float2half_rn(sm_[threadIdx.x][threadIdx.y]);
}
__global__ void transpose_rest(const float* __restrict__ wp, const float* __restrict__ w1,
                               const float* __restrict__ w2, __half* __restrict__ out) {
    __shared__ float sm_[32][33];
    int idx = blockIdx.x;
    const float* in; __half* o; int K, N, n0, k0;
    if (idx < 1024) {                        // proj: [1024,1024]
        in = wp; o = out + 3 * 1024 * 1024; K = 1024; N = 1024;
        n0 = (idx & 31) * 32; k0 = (idx >> 5) * 32;
    } else if (idx < 1024 + 4096) {          // w1: [1024,4096]
        int t = idx - 1024;
        in = w1; o = out + 4 * 1024 * 1024; K = 1024; N = 4096;
        n0 = (t & 127) * 32; k0 = (t >> 7) * 32;
    } else {                                 // w2: [4096,1024]
        int t = idx - 5120;
        in = w2; o = out + 8 * 1024 * 1024; K = 4096; N = 1024;
        n0 = (t & 31) * 32; k0 = (t >> 5) * 32;
    }
    sm_[threadIdx.y][threadIdx.x] = in[(size_t)(k0 + threadIdx.y) * N + n0 + threadIdx.x];
    __syncthreads();
    o[(size_t)(n0 + threadIdx.y) * K + k0 + threadIdx.x] =
        __float2half_rn(sm_[threadIdx.x][threadIdx.y]);
}

// ---------------- layernorm (fp32 in, fp16 out) -----------------------------
__global__ void ln_kernel(const float* __restrict__ x, const float* __restrict__ g,
                          const float* __restrict__ b, __half* __restrict__ out) {
    int row = blockIdx.x;
    const float* xr = x + (size_t)row * DD;
    float vv[4];
    float s = 0.f, sq = 0.f;
#pragma unroll
    for (int i = 0; i < 4; i++) {
        float t = xr[threadIdx.x + i * 256];
        vv[i] = t; s += t; sq += t * t;
    }
    __shared__ float red[64];
#pragma unroll
    for (int o = 16; o > 0; o >>= 1) {
        s  += __shfl_xor_sync(0xffffffffu, s, o);
        sq += __shfl_xor_sync(0xffffffffu, sq, o);
    }
    int warp = threadIdx.x >> 5, lane = threadIdx.x & 31;
    if (lane == 0) { red[warp] = s; red[warp + 8] = sq; }
    __syncthreads();
    if (threadIdx.x < 32) {
        float ss = (threadIdx.x < 8) ? red[threadIdx.x] : 0.f;
        float qq = (threadIdx.x < 8) ? red[threadIdx.x + 8] : 0.f;
#pragma unroll
        for (int o = 4; o > 0; o >>= 1) {
            ss += __shfl_xor_sync(0xffffffffu, ss, o);
            qq += __shfl_xor_sync(0xffffffffu, qq, o);
        }
        if (threadIdx.x == 0) { red[32] = ss; red[33] = qq; }
    }
    __syncthreads();
    float mean = red[32] * (1.f / DD);
    float var  = red[33] * (1.f / DD) - mean * mean;
    float inv  = rsqrtf(var + 1e-5f);
#pragma unroll
    for (int i = 0; i < 4; i++) {
        int c = threadIdx.x + i * 256;
        out[(size_t)row * DD + c] = __float2half_rn((vv[i] - mean) * inv * g[c] + b[c]);
    }
}

// ---------------- fp16 mma GEMM: C = A[MxK] @ Bt[NxK]^T ---------------------
// 128x128 CTA tile, BK=32, 3-stage cp.async, single sync/chunk
// (load-after-compute). 4 warps (2x2), warp tile 64x64, 2 CTAs/SM.
// (Round-11 validated config — 256x128/1-CTA and all depth/BK variants regressed.)
#define GS 3
#define SPITCH 40                    // halfs per 32-col row (80B, LDSM-conflict-free)
#define STGH (2*128*SPITCH)          // halfs per stage (A+B)
#define ATILEH (128*SPITCH)

__device__ __forceinline__ void ld_stage(__half* sA, const __half* Ag, const __half* Bg,
                                         int K, int tid) {
#pragma unroll
    for (int i = 0; i < 4; i++) {
        int j = tid + (i << 7);               // 0..511 16B units (A)
        int r = j >> 2, q = j & 3;
        cpa(s2u(sA + r * SPITCH + q * 8), Ag + (size_t)r * K + q * 8);
    }
    __half* sB = sA + ATILEH;
#pragma unroll
    for (int i = 0; i < 4; i++) {
        int j = tid + (i << 7);
        int r = j >> 2, q = j & 3;
        cpa(s2u(sB + r * SPITCH + q * 8), Bg + (size_t)r * K + q * 8);
    }
}

template<bool HOUT, bool BIAS, bool RELU, bool RES>
__global__ __launch_bounds__(128, 2)
void tc_gemm(const __half* __restrict__ A, const __half* __restrict__ Bt,
             const float* __restrict__ bias, const float* __restrict__ res,
             void* __restrict__ Cv, int M, int N, int K) {
    extern __shared__ __half sm[];
    int tid = threadIdx.x, wid = tid >> 5, lane = tid & 31;
    int wm = wid >> 1, wn = wid & 1;          // warp grid 2(M) x 2(N), 64x64 tiles
    int g = lane >> 2, tig = lane & 3;
    int n0 = blockIdx.x * 128, m0 = blockIdx.y * 128;

    const __half* Ab = A + (size_t)m0 * K;
    const __half* Bb = Bt + (size_t)n0 * K;
    int nch = K >> 5;

    float acc[4][8][4] = {};                  // i(16-row) x j(8-col) x frag

    // prologue: 2 chunks in flight
#pragma unroll
    for (int c = 0; c < GS - 1; c++) {
        ld_stage(sm + c * STGH, Ab + c * 32, Bb + c * 32, K, tid);
        CP_COMMIT();
    }

    for (int c = 0; c < nch; c++) {
        cp_wait<GS - 2>();          // chunk c's load complete
        __syncthreads();            // all warps done reading buffer (c-1)%GS
        __half* sA = sm + (c % GS) * STGH;
        __half* sB = sA + ATILEH;

        uint32_t bk[8][2][2];
#pragma unroll
        for (int j = 0; j < 8; j++) {
            uint32_t a = s2u(sB + (wn * 64 + j * 8 + (lane & 7)) * SPITCH
                             + ((lane >> 3) & 3) * 8);
            LDSM4(bk[j][0][0], bk[j][0][1], bk[j][1][0], bk[j][1][1], a);
        }
#pragma unroll
        for (int kk = 0; kk < 2; kk++) {
            uint32_t af[4][4];
#pragma unroll
            for (int i = 0; i < 4; i++) {
                uint32_t a = s2u(sA + (wm * 64 + i * 16 + (lane & 15)) * SPITCH
                                 + kk * 16 + (lane >> 4) * 8);
                LDSM4(af[i][0], af[i][1], af[i][2], af[i][3], a);
            }
#pragma unroll
            for (int i = 0; i < 4; i++)
#pragma unroll
                for (int j = 0; j < 8; j++)
                    mma_f16(acc[i][j], af[i], bk[j][kk]);
        }

        // issue next load AFTER compute; target buffer (c+2)%3 held chunk c-1,
        // whose reads finished before this iteration's barrier.
        if (c + GS - 1 < nch)
            ld_stage(sm + ((c + GS - 1) % GS) * STGH,
                     Ab + (size_t)(c + GS - 1) * 32,
                     Bb + (size_t)(c + GS - 1) * 32, K, tid);
        CP_COMMIT();
    }

    // epilogue
#pragma unroll
    for (int i = 0; i < 4; i++) {
        int m_up = m0 + wm * 64 + i * 16 + g;
#pragma unroll
        for (int j = 0; j < 8; j++) {
            int n = n0 + wn * 64 + j * 8 + 2 * tig;
            float v0 = acc[i][j][0], v1 = acc[i][j][1];
            float v2 = acc[i][j][2], v3 = acc[i][j][3];
            if (BIAS) {
                float2 bv = *(const float2*)(bias + n);
                v0 += bv.x; v1 += bv.y; v2 += bv.x; v3 += bv.y;
            }
            if (RELU) {
                v0 = fmaxf(v0, 0.f); v1 = fmaxf(v1, 0.f);
                v2 = fmaxf(v2, 0.f); v3 = fmaxf(v3, 0.f);
            }
            if (RES) {
                float2 r0 = *(const float2*)(res + (size_t)m_up * N + n);
                float2 r1 = *(const float2*)(res + (size_t)(m_up + 8) * N + n);
                v0 += r0.x; v1 += r0.y; v2 += r1.x; v3 += r1.y;
            }
            if (HOUT) {
                __half* C = (__half*)Cv;
                *(__half2*)(C + (size_t)m_up * N + n) = __floats2half2_rn(v0, v1);
                *(__half2*)(C + (size_t)(m_up + 8) * N + n) = __floats2half2_rn(v2, v3);
            } else {
                float* C = (float*)Cv;
                *(float2*)(C + (size_t)m_up * N + n) = make_float2(v0, v1);
                *(float2*)(C + (size_t)(m_up + 8) * N + n) = make_float2(v2, v3);
            }
        }
    }
}

// ---------------- fp16 mma causal flash attention ---------------------------
// Q tile 128 rows (8 warps x 16), K/V tiles 64 rows double-buffered.
// Heavy-first schedule. NEW: next-tile loads issue AFTER the QK^T MMA block
// (round-8 GEMM lesson: defer cp.async issue past the first compute block).
#define APITCH 72
#define AQ_OFF 0
#define AK_OFF (128*APITCH)
#define AV_OFF (AK_OFF + 2*64*APITCH)
#define ASMEM_HALFS (AV_OFF + 2*64*APITCH)
#define SCL 0.18033688011112042f     // 0.125 * log2(e)

__device__ __forceinline__ void attn_ld_kv(__half* sm, int buf,
                                           const __half* kb, const __half* vb,
                                           int jt, int tid) {
    __half* Kd = sm + AK_OFF + buf * 64 * APITCH;
    __half* Vd = sm + AV_OFF + buf * 64 * APITCH;
#pragma unroll
    for (int i = 0; i < 2; i++) {
        int j = tid + (i << 8);
        int r = j >> 3, q = j & 7;
        size_t gr = (size_t)(jt * 64 + r) * QLD + q * 8;
        cpa(s2u(Kd + r * APITCH + q * 8), kb + gr);
        cpa(s2u(Vd + r * APITCH + q * 8), vb + gr);
    }
}

__global__ __launch_bounds__(256)
void attn_kernel(const __half* __restrict__ qkv, __half* __restrict__ ctx) {
    extern __shared__ __half smA[];
    __half* Qs = smA + AQ_OFF;

    int qt = (int)(gridDim.x - 1 - blockIdx.x);    // heavy tiles first
    int bh = blockIdx.y;
    int b = bh >> 4, h = bh & 15;
    int tid = threadIdx.x, w = tid >> 5, lane = tid & 31;
    int g = lane >> 2, t = lane & 3;

    const __half* qb = qkv + ((size_t)(b * TT) + qt * 128) * QLD + h * 64;
    const __half* kb = qkv + (size_t)(b * TT) * QLD + DD + h * 64;
    const __half* vb = kb + DD;

    // load Q tile (128 rows x 64 cols)
#pragma unroll
    for (int i = 0; i < 4; i++) {
        int j = tid + (i << 8);
        int r = j >> 3, q = j & 7;
        cpa(s2u(Qs + r * APITCH + q * 8), qb + (size_t)r * QLD + q * 8);
    }
    CP_COMMIT();
    cp_wait<0>();
    __syncthreads();

    uint32_t qf[4][4];
#pragma unroll
    for (int kk = 0; kk < 4; kk++) {
        uint32_t a = s2u(Qs + (w * 16 + (lane & 15)) * APITCH + kk * 16 + (lane >> 4) * 8);
        LDSM4(qf[kk][0], qf[kk][1], qf[kk][2], qf[kk][3], a);
    }

    float o[8][4] = {};
    float m0 = -1e30f, m1 = -1e30f, l0 = 0.f, l1 = 0.f;
    int row0 = qt * 128 + w * 16 + g, row1 = row0 + 8;
    int wmax = qt * 128 + w * 16 + 15;      // largest q-row in this warp
    int ntiles = 2 * qt + 2;

    attn_ld_kv(smA, 0, kb, vb, 0, tid);
    CP_COMMIT();

    for (int jt = 0; jt < ntiles; jt++) {
        cp_wait<0>();
        __syncthreads();
        int cur = jt & 1;
        bool active = (jt * 64 <= wmax);
        __half* Ks = smA + AK_OFF + cur * 64 * APITCH;
        __half* Vs = smA + AV_OFF + cur * 64 * APITCH;

        // S = Q @ K^T (first compute block)
        float s[8][4] = {};
        if (active) {
#pragma unroll
            for (int j = 0; j < 8; j++) {
                uint32_t bb[4][2];
                uint32_t a0 = s2u(Ks + (j * 8 + (lane & 7)) * APITCH + ((lane >> 3) & 3) * 8);
                LDSM4(bb[0][0], bb[0][1], bb[1][0], bb[1][1], a0);
                LDSM4(bb[2][0], bb[2][1], bb[3][0], bb[3][1], a0 + 64);
#pragma unroll
                for (int kk = 0; kk < 4; kk++) mma_f16(s[j], qf[kk], bb[kk]);
            }
        }

        // issue next-tile loads AFTER the QK^T block; target buffer held jt-1,
        // whose reads finished before this iteration's barrier.
        if (jt + 1 < ntiles)
            attn_ld_kv(smA, (jt + 1) & 1, kb, vb, jt + 1, tid);
        CP_COMMIT();

        if (active) {
            // scale (log2 domain) + causal mask
            bool anymask = (jt * 64 + 63 > row0);
#pragma unroll
            for (int j = 0; j < 8; j++) {
                s[j][0] *= SCL; s[j][1] *= SCL;
                s[j][2] *= SCL; s[j][3] *= SCL;
                if (anymask) {
                    int c0 = jt * 64 + j * 8 + 2 * t;
                    if (c0 > row0)     s[j][0] = -1e30f;
                    if (c0 + 1 > row0) s[j][1] = -1e30f;
                    if (c0 > row1)     s[j][2] = -1e30f;
                    if (c0 + 1 > row1) s[j][3] = -1e30f;
                }
            }

            // online softmax (log2 domain)
            float mx0 = -1e30f, mx1 = -1e30f;
#pragma unroll
            for (int j = 0; j < 8; j++) {
                mx0 = fmaxf(mx0, fmaxf(s[j][0], s[j][1]));
                mx1 = fmaxf(mx1, fmaxf(s[j][2], s[j][3]));
            }
            mx0 = fmaxf(mx0, __shfl_xor_sync(0xffffffffu, mx0, 1));
            mx0 = fmaxf(mx0, __shfl_xor_sync(0xffffffffu, mx0, 2));
            mx1 = fmaxf(mx1, __shfl_xor_sync(0xffffffffu, mx1, 1));
            mx1 = fmaxf(mx1, __shfl_xor_sync(0xffffffffu, mx1, 2));
            float mn0 = fmaxf(m0, mx0), mn1 = fmaxf(m1, mx1);
            float f0 = ex2(m0 - mn0), f1 = ex2(m1 - mn1);
            float sum0 = 0.f, sum1 = 0.f;
#pragma unroll
            for (int j = 0; j < 8; j++) {
                s[j][0] = ex2(s[j][0] - mn0);
                s[j][1] = ex2(s[j][1] - mn0);
                s[j][2] = ex2(s[j][2] - mn1);
                s[j][3] = ex2(s[j][3] - mn1);
                sum0 += s[j][0] + s[j][1];
                sum1 += s[j][2] + s[j][3];
            }
            sum0 += __shfl_xor_sync(0xffffffffu, sum0, 1);
            sum0 += __shfl_xor_sync(0xffffffffu, sum0, 2);
            sum1 += __shfl_xor_sync(0xffffffffu, sum1, 1);
            sum1 += __shfl_xor_sync(0xffffffffu, sum1, 2);
            l0 = l0 * f0 + sum0; l1 = l1 * f1 + sum1;
            m0 = mn0; m1 = mn1;
#pragma unroll
            for (int jo = 0; jo < 8; jo++) {
                o[jo][0] *= f0; o[jo][1] *= f0;
                o[jo][2] *= f1; o[jo][3] *= f1;
            }

            // O += P @ V
#pragma unroll
            for (int kk = 0; kk < 4; kk++) {
                uint32_t ap[4];
                ap[0] = pkh2(s[2*kk][0],   s[2*kk][1]);
                ap[1] = pkh2(s[2*kk][2],   s[2*kk][3]);
                ap[2] = pkh2(s[2*kk+1][0], s[2*kk+1][1]);
                ap[3] = pkh2(s[2*kk+1][2], s[2*kk+1][3]);
#pragma unroll
                for (int hb = 0; hb < 4; hb++) {
                    uint32_t bv[4];
                    uint32_t a = s2u(Vs + (kk * 16 + (lane & 15)) * APITCH
                                     + hb * 16 + (lane >> 4) * 8);
                    LDSM4T(bv[0], bv[1], bv[2], bv[3], a);
                    mma_f16(o[hb * 2],     ap, bv);
                    mma_f16(o[hb * 2 + 1], ap, bv + 2);
                }
            }
        }
    }

    float inv0 = 1.f / l0, inv1 = 1.f / l1;
    __half* c0 = ctx + ((size_t)(b * TT) + row0) * DD + h * 64;
    __half* c1 = ctx + ((size_t)(b * TT) + row1) * DD + h * 64;
#pragma unroll
    for (int jo = 0; jo < 8; jo++) {
        int col = jo * 8 + 2 * t;
        *(__half2*)(c0 + col) = __floats2half2_rn(o[jo][0] * inv0, o[jo][1] * inv0);
        *(__half2*)(c1 + col) = __floats2half2_rn(o[jo][2] * inv1, o[jo][3] * inv1);
    }
}

// ---------------- launcher --------------------------------------------------
extern "C" void kernel_launch(void* const* d_in, const int* in_sizes, int n_in,
                              void* d_out, int out_size) {
    const float* x      = (const float*)d_in[0];
    const float* ln1_g  = (const float*)d_in[1];
    const float* ln1_b  = (const float*)d_in[2];
    const float* wq     = (const float*)d_in[3];
    const float* wk     = (const float*)d_in[4];
    const float* wv     = (const float*)d_in[5];
    const float* w_proj = (const float*)d_in[6];
    const float* b_proj = (const float*)d_in[7];
    const float* ln2_g  = (const float*)d_in[8];
    const float* ln2_b  = (const float*)d_in[9];
    const float* w1     = (const float*)d_in[10];
    const float* b1     = (const float*)d_in[11];
    const float* w2     = (const float*)d_in[12];
    const float* b2     = (const float*)d_in[13];
    float* out = (float*)d_out;

    __half *xn, *qkv, *ctx, *hb, *w;
    float *x1;
    cudaGetSymbolAddress((void**)&xn,  g_xn);
    cudaGetSymbolAddress((void**)&qkv, g_qkv);
    cudaGetSymbolAddress((void**)&ctx, g_ctx);
    cudaGetSymbolAddress((void**)&x1,  g_x1);
    cudaGetSymbolAddress((void**)&hb,  g_h);
    cudaGetSymbolAddress((void**)&w,   g_w);
    __half* wqkv = w;                      // [3072, 1024]
    __half* wpro = w + 3 * 1024 * 1024;    // [1024, 1024]
    __half* w1t  = w + 4 * 1024 * 1024;    // [4096, 1024]
    __half* w2t  = w + 8 * 1024 * 1024;    // [1024, 4096]

    const size_t GSMEM = (size_t)GS * STGH * sizeof(__half);          // 61440
    const size_t ASMEM = (size_t)ASMEM_HALFS * sizeof(__half);        // 55296
    cudaFuncSetAttribute(tc_gemm<true ,false,false,false>, cudaFuncAttributeMaxDynamicSharedMemorySize, GSMEM);
    cudaFuncSetAttribute(tc_gemm<false,true ,false,true >, cudaFuncAttributeMaxDynamicSharedMemorySize, GSMEM);
    cudaFuncSetAttribute(tc_gemm<true ,true ,true ,false>, cudaFuncAttributeMaxDynamicSharedMemorySize, GSMEM);
    cudaFuncSetAttribute(attn_kernel, cudaFuncAttributeMaxDynamicSharedMemorySize, ASMEM);

    dim3 tb(32, 32);
    // (1) LN1 (needs only x)
    ln_kernel<<<BT, 256>>>(x, ln1_g, ln1_b, xn);
    // (2) qkv weight repack
    transpose_qkv3<<<dim3(32, 2, 48), tb>>>(wq, wk, wv, wqkv);
    // (3) fused QKV projection: [8192, 3072] fp16 out
    tc_gemm<true,false,false,false><<<dim3(24, 64), 128, GSMEM>>>(
        xn, wqkv, nullptr, nullptr, qkv, BT, 3 * DD, DD);
    // (4) attention (fp16 mma flash, 128-row Q tiles, heavy-first)  [profiled]
    attn_kernel<<<dim3(TT / 128, BB * HH), 256, ASMEM>>>(qkv, ctx);
    // (5) proj/w1/w2 repack (single launch)
    transpose_rest<<<9216, tb>>>(w_proj, w1, w2, w);
    // (6) output projection + bias + residual -> x1 fp32
    tc_gemm<false,true,false,true><<<dim3(8, 64), 128, GSMEM>>>(
        ctx, wpro, b_proj, x, x1, BT, DD, DD);
    // (7) LN2
    ln_kernel<<<BT, 256>>>(x1, ln2_g, ln2_b, xn);
    // (8) FFN1: relu(xn @ w1 + b1) -> h fp16
    tc_gemm<true,true,true,false><<<dim3(32, 64), 128, GSMEM>>>(
        xn, w1t, b1, nullptr, hb, BT, FF, DD);
    // (9) FFN2: h @ w2 + b2 + x1 -> out fp32
    tc_gemm<false,true,false,true><<<dim3(8, 64), 128, GSMEM>>>(
        hb, w2t, b2, x1, out, BT, DD, FF);
}

// round 14
// speedup vs baseline: 1.1547x; 1.0062x over previous
#include <cuda_runtime.h>
#include <cuda_fp16.h>
#include <math.h>
#include <stdint.h>

#define BB   4
#define TT   2048
#define DD   1024
#define HH   16
#define HSV  64
#define FF   4096
#define BT   (BB*TT)
#define QLD  (3*DD)          // packed qkv row stride (halfs)

// ---------------- scratch (device globals; no runtime allocation) ----------
__device__ __half g_xn [BT*DD];
__device__ __half g_qkv[(size_t)BT*3*DD];
__device__ __half g_ctx[BT*DD];
__device__ float  g_x1 [BT*DD];
__device__ __half g_h  [(size_t)BT*FF];
__device__ __half g_w  [12*1024*1024];   // qkv' 3M | proj' 1M | w1' 4M | w2' 4M

// ---------------- small helpers --------------------------------------------
__device__ __forceinline__ uint32_t s2u(const void* p) {
    return (uint32_t)__cvta_generic_to_shared(p);
}
__device__ __forceinline__ uint32_t pkh2(float a, float b) {
    __half2 h = __floats2half2_rn(a, b);
    return *reinterpret_cast<uint32_t*>(&h);
}
__device__ __forceinline__ float ex2(float x) {
    float r;
    asm("ex2.approx.ftz.f32 %0, %1;" : "=f"(r) : "f"(x));
    return r;
}
__device__ __forceinline__ void mma_f16(float* c, const uint32_t* a, const uint32_t* b) {
    asm volatile(
        "mma.sync.aligned.m16n8k16.row.col.f32.f16.f16.f32 "
        "{%0,%1,%2,%3}, {%4,%5,%6,%7}, {%8,%9}, {%0,%1,%2,%3};"
        : "+f"(c[0]), "+f"(c[1]), "+f"(c[2]), "+f"(c[3])
        : "r"(a[0]), "r"(a[1]), "r"(a[2]), "r"(a[3]), "r"(b[0]), "r"(b[1]));
}
#define LDSM4(r0,r1,r2,r3,a) \
    asm volatile("ldmatrix.sync.aligned.m8n8.x4.shared.b16 {%0,%1,%2,%3}, [%4];" \
        : "=r"(r0),"=r"(r1),"=r"(r2),"=r"(r3) : "r"(a))
#define LDSM4T(r0,r1,r2,r3,a) \
    asm volatile("ldmatrix.sync.aligned.m8n8.x4.trans.shared.b16 {%0,%1,%2,%3}, [%4];" \
        : "=r"(r0),"=r"(r1),"=r"(r2),"=r"(r3) : "r"(a))
__device__ __forceinline__ void cpa(uint32_t dst, const void* src) {
    asm volatile("cp.async.cg.shared.global [%0], [%1], 16;"
                 :: "r"(dst), "l"(src) : "memory");
}
#define CP_COMMIT() asm volatile("cp.async.commit_group;" ::: "memory")
template<int N> __device__ __forceinline__ void cp_wait() {
    asm volatile("cp.async.wait_group %0;" :: "n"(N) : "memory");
}

// ---------------- weight repack kernels (fp32 -> fp16) ----------------------
__global__ void transpose_qkv3(const float* __restrict__ wq, const float* __restrict__ wk,
                               const float* __restrict__ wv, __half* __restrict__ out) {
    __shared__ float sm_[32][33];
    int z = blockIdx.z;
    int which = z >> 4, h = z & 15;
    const float* w = (which == 0) ? wq : (which == 1) ? wk : wv;
    __half* o = out + (size_t)which * DD * DD;
    int d0 = blockIdx.x * 32, j0 = blockIdx.y * 32;
    sm_[threadIdx.y][threadIdx.x] =
        w[((size_t)h * DD + d0 + threadIdx.y) * HSV + j0 + threadIdx.x];
    __syncthreads();
    o[(size_t)(h * HSV + j0 + threadIdx.y) * DD + d0 + threadIdx.x] =
        __float2half_rn(sm_[threadIdx.x][threadIdx.y]);
}
__global__ void transpose_rest(const float* __restrict__ wp, const float* __restrict__ w1,
                               const float* __restrict__ w2, __half* __restrict__ out) {
    __shared__ float sm_[32][33];
    int idx = blockIdx.x;
    const float* in; __half* o; int K, N, n0, k0;
    if (idx < 1024) {                        // proj: [1024,1024]
        in = wp; o = out + 3 * 1024 * 1024; K = 1024; N = 1024;
        n0 = (idx & 31) * 32; k0 = (idx >> 5) * 32;
    } else if (idx < 1024 + 4096) {          // w1: [1024,4096]
        int t = idx - 1024;
        in = w1; o = out + 4 * 1024 * 1024; K = 1024; N = 4096;
        n0 = (t & 127) * 32; k0 = (t >> 7) * 32;
    } else {                                 // w2: [4096,1024]
        int t = idx - 5120;
        in = w2; o = out + 8 * 1024 * 1024; K = 4096; N = 1024;
        n0 = (t & 31) * 32; k0 = (t >> 5) * 32;
    }
    sm_[threadIdx.y][threadIdx.x] = in[(size_t)(k0 + threadIdx.y) * N + n0 + threadIdx.x];
    __syncthreads();
    o[(size_t)(n0 + threadIdx.y) * K + k0 + threadIdx.x] =
        __float2half_rn(sm_[threadIdx.x][threadIdx.y]);
}

// ---------------- layernorm (fp32 in, fp16 out) -----------------------------
__global__ void ln_kernel(const float* __restrict__ x, const float* __restrict__ g,
                          const float* __restrict__ b, __half* __restrict__ out) {
    int row = blockIdx.x;
    const float* xr = x + (size_t)row * DD;
    float vv[4];
    float s = 0.f, sq = 0.f;
#pragma unroll
    for (int i = 0; i < 4; i++) {
        float t = xr[threadIdx.x + i * 256];
        vv[i] = t; s += t; sq += t * t;
    }
    __shared__ float red[64];
#pragma unroll
    for (int o = 16; o > 0; o >>= 1) {
        s  += __shfl_xor_sync(0xffffffffu, s, o);
        sq += __shfl_xor_sync(0xffffffffu, sq, o);
    }
    int warp = threadIdx.x >> 5, lane = threadIdx.x & 31;
    if (lane == 0) { red[warp] = s; red[warp + 8] = sq; }
    __syncthreads();
    if (threadIdx.x < 32) {
        float ss = (threadIdx.x < 8) ? red[threadIdx.x] : 0.f;
        float qq = (threadIdx.x < 8) ? red[threadIdx.x + 8] : 0.f;
#pragma unroll
        for (int o = 4; o > 0; o >>= 1) {
            ss += __shfl_xor_sync(0xffffffffu, ss, o);
            qq += __shfl_xor_sync(0xffffffffu, qq, o);
        }
        if (threadIdx.x == 0) { red[32] = ss; red[33] = qq; }
    }
    __syncthreads();
    float mean = red[32] * (1.f / DD);
    float var  = red[33] * (1.f / DD) - mean * mean;
    float inv  = rsqrtf(var + 1e-5f);
#pragma unroll
    for (int i = 0; i < 4; i++) {
        int c = threadIdx.x + i * 256;
        out[(size_t)row * DD + c] = __float2half_rn((vv[i] - mean) * inv * g[c] + b[c]);
    }
}

// ---------------- fp16 mma GEMM: C = A[MxK] @ Bt[NxK]^T ---------------------
// 128x128 CTA tile, BK=32, 3-stage cp.async, single sync/chunk
// (load-after-compute). 4 warps (2x2), warp tile 64x64, 2 CTAs/SM.
// (Round-11 validated config — 256x128/1-CTA and all depth/BK variants regressed.)
#define GS 3
#define SPITCH 40                    // halfs per 32-col row (80B, LDSM-conflict-free)
#define STGH (2*128*SPITCH)          // halfs per stage (A+B)
#define ATILEH (128*SPITCH)

__device__ __forceinline__ void ld_stage(__half* sA, const __half* Ag, const __half* Bg,
                                         int K, int tid) {
#pragma unroll
    for (int i = 0; i < 4; i++) {
        int j = tid + (i << 7);               // 0..511 16B units (A)
        int r = j >> 2, q = j & 3;
        cpa(s2u(sA + r * SPITCH + q * 8), Ag + (size_t)r * K + q * 8);
    }
    __half* sB = sA + ATILEH;
#pragma unroll
    for (int i = 0; i < 4; i++) {
        int j = tid + (i << 7);
        int r = j >> 2, q = j & 3;
        cpa(s2u(sB + r * SPITCH + q * 8), Bg + (size_t)r * K + q * 8);
    }
}

template<bool HOUT, bool BIAS, bool RELU, bool RES>
__global__ __launch_bounds__(128, 2)
void tc_gemm(const __half* __restrict__ A, const __half* __restrict__ Bt,
             const float* __restrict__ bias, const float* __restrict__ res,
             void* __restrict__ Cv, int M, int N, int K) {
    extern __shared__ __half sm[];
    int tid = threadIdx.x, wid = tid >> 5, lane = tid & 31;
    int wm = wid >> 1, wn = wid & 1;          // warp grid 2(M) x 2(N), 64x64 tiles
    int g = lane >> 2, tig = lane & 3;
    int n0 = blockIdx.x * 128, m0 = blockIdx.y * 128;

    const __half* Ab = A + (size_t)m0 * K;
    const __half* Bb = Bt + (size_t)n0 * K;
    int nch = K >> 5;

    float acc[4][8][4] = {};                  // i(16-row) x j(8-col) x frag

    // prologue: 2 chunks in flight
#pragma unroll
    for (int c = 0; c < GS - 1; c++) {
        ld_stage(sm + c * STGH, Ab + c * 32, Bb + c * 32, K, tid);
        CP_COMMIT();
    }

    for (int c = 0; c < nch; c++) {
        cp_wait<GS - 2>();          // chunk c's load complete
        __syncthreads();            // all warps done reading buffer (c-1)%GS
        __half* sA = sm + (c % GS) * STGH;
        __half* sB = sA + ATILEH;

        uint32_t bk[8][2][2];
#pragma unroll
        for (int j = 0; j < 8; j++) {
            uint32_t a = s2u(sB + (wn * 64 + j * 8 + (lane & 7)) * SPITCH
                             + ((lane >> 3) & 3) * 8);
            LDSM4(bk[j][0][0], bk[j][0][1], bk[j][1][0], bk[j][1][1], a);
        }
#pragma unroll
        for (int kk = 0; kk < 2; kk++) {
            uint32_t af[4][4];
#pragma unroll
            for (int i = 0; i < 4; i++) {
                uint32_t a = s2u(sA + (wm * 64 + i * 16 + (lane & 15)) * SPITCH
                                 + kk * 16 + (lane >> 4) * 8);
                LDSM4(af[i][0], af[i][1], af[i][2], af[i][3], a);
            }
#pragma unroll
            for (int i = 0; i < 4; i++)
#pragma unroll
                for (int j = 0; j < 8; j++)
                    mma_f16(acc[i][j], af[i], bk[j][kk]);
        }

        // issue next load AFTER compute; target buffer (c+2)%3 held chunk c-1,
        // whose reads finished before this iteration's barrier.
        if (c + GS - 1 < nch)
            ld_stage(sm + ((c + GS - 1) % GS) * STGH,
                     Ab + (size_t)(c + GS - 1) * 32,
                     Bb + (size_t)(c + GS - 1) * 32, K, tid);
        CP_COMMIT();
    }

    // epilogue
#pragma unroll
    for (int i = 0; i < 4; i++) {
        int m_up = m0 + wm * 64 + i * 16 + g;
#pragma unroll
        for (int j = 0; j < 8; j++) {
            int n = n0 + wn * 64 + j * 8 + 2 * tig;
            float v0 = acc[i][j][0], v1 = acc[i][j][1];
            float v2 = acc[i][j][2], v3 = acc[i][j][3];
            if (BIAS) {
                float2 bv = *(const float2*)(bias + n);
                v0 += bv.x; v1 += bv.y; v2 += bv.x; v3 += bv.y;
            }
            if (RELU) {
                v0 = fmaxf(v0, 0.f); v1 = fmaxf(v1, 0.f);
                v2 = fmaxf(v2, 0.f); v3 = fmaxf(v3, 0.f);
            }
            if (RES) {
                float2 r0 = *(const float2*)(res + (size_t)m_up * N + n);
                float2 r1 = *(const float2*)(res + (size_t)(m_up + 8) * N + n);
                v0 += r0.x; v1 += r0.y; v2 += r1.x; v3 += r1.y;
            }
            if (HOUT) {
                __half* C = (__half*)Cv;
                *(__half2*)(C + (size_t)m_up * N + n) = __floats2half2_rn(v0, v1);
                *(__half2*)(C + (size_t)(m_up + 8) * N + n) = __floats2half2_rn(v2, v3);
            } else {
                float* C = (float*)Cv;
                *(float2*)(C + (size_t)m_up * N + n) = make_float2(v0, v1);
                *(float2*)(C + (size_t)(m_up + 8) * N + n) = make_float2(v2, v3);
            }
        }
    }
}

// ---------------- fp16 mma causal flash attention ---------------------------
// Q tile 128 rows (8 warps x 16), K/V tiles 64 rows double-buffered.
// Heavy-first schedule. NEW: next-tile loads issue AFTER the QK^T MMA block
// (round-8 GEMM lesson: defer cp.async issue past the first compute block).
#define APITCH 72
#define AQ_OFF 0
#define AK_OFF (128*APITCH)
#define AV_OFF (AK_OFF + 2*64*APITCH)
#define ASMEM_HALFS (AV_OFF + 2*64*APITCH)
#define SCL 0.18033688011112042f     // 0.125 * log2(e)

__device__ __forceinline__ void attn_ld_kv(__half* sm, int buf,
                                           const __half* kb, const __half* vb,
                                           int jt, int tid) {
    __half* Kd = sm + AK_OFF + buf * 64 * APITCH;
    __half* Vd = sm + AV_OFF + buf * 64 * APITCH;
#pragma unroll
    for (int i = 0; i < 2; i++) {
        int j = tid + (i << 8);
        int r = j >> 3, q = j & 7;
        size_t gr = (size_t)(jt * 64 + r) * QLD + q * 8;
        cpa(s2u(Kd + r * APITCH + q * 8), kb + gr);
        cpa(s2u(Vd + r * APITCH + q * 8), vb + gr);
    }
}

__global__ __launch_bounds__(256)
void attn_kernel(const __half* __restrict__ qkv, __half* __restrict__ ctx) {
    extern __shared__ __half smA[];
    __half* Qs = smA + AQ_OFF;

    int qt = (int)(gridDim.x - 1 - blockIdx.x);    // heavy tiles first
    int bh = blockIdx.y;
    int b = bh >> 4, h = bh & 15;
    int tid = threadIdx.x, w = tid >> 5, lane = tid & 31;
    int g = lane >> 2, t = lane & 3;

    const __half* qb = qkv + ((size_t)(b * TT) + qt * 128) * QLD + h * 64;
    const __half* kb = qkv + (size_t)(b * TT) * QLD + DD + h * 64;
    const __half* vb = kb + DD;

    // load Q tile (128 rows x 64 cols)
#pragma unroll
    for (int i = 0; i < 4; i++) {
        int j = tid + (i << 8);
        int r = j >> 3, q = j & 7;
        cpa(s2u(Qs + r * APITCH + q * 8), qb + (size_t)r * QLD + q * 8);
    }
    CP_COMMIT();
    cp_wait<0>();
    __syncthreads();

    uint32_t qf[4][4];
#pragma unroll
    for (int kk = 0; kk < 4; kk++) {
        uint32_t a = s2u(Qs + (w * 16 + (lane & 15)) * APITCH + kk * 16 + (lane >> 4) * 8);
        LDSM4(qf[kk][0], qf[kk][1], qf[kk][2], qf[kk][3], a);
    }

    float o[8][4] = {};
    float m0 = -1e30f, m1 = -1e30f, l0 = 0.f, l1 = 0.f;
    int row0 = qt * 128 + w * 16 + g, row1 = row0 + 8;
    int wmax = qt * 128 + w * 16 + 15;      // largest q-row in this warp
    int ntiles = 2 * qt + 2;

    attn_ld_kv(smA, 0, kb, vb, 0, tid);
    CP_COMMIT();

    for (int jt = 0; jt < ntiles; jt++) {
        cp_wait<0>();
        __syncthreads();
        int cur = jt & 1;
        bool active = (jt * 64 <= wmax);
        __half* Ks = smA + AK_OFF + cur * 64 * APITCH;
        __half* Vs = smA + AV_OFF + cur * 64 * APITCH;

        // S = Q @ K^T (first compute block)
        float s[8][4] = {};
        if (active) {
#pragma unroll
            for (int j = 0; j < 8; j++) {
                uint32_t bb[4][2];
                uint32_t a0 = s2u(Ks + (j * 8 + (lane & 7)) * APITCH + ((lane >> 3) & 3) * 8);
                LDSM4(bb[0][0], bb[0][1], bb[1][0], bb[1][1], a0);
                LDSM4(bb[2][0], bb[2][1], bb[3][0], bb[3][1], a0 + 64);
#pragma unroll
                for (int kk = 0; kk < 4; kk++) mma_f16(s[j], qf[kk], bb[kk]);
            }
        }

        // issue next-tile loads AFTER the QK^T block; target buffer held jt-1,
        // whose reads finished before this iteration's barrier.
        if (jt + 1 < ntiles)
            attn_ld_kv(smA, (jt + 1) & 1, kb, vb, jt + 1, tid);
        CP_COMMIT();

        if (active) {
            // scale (log2 domain) + causal mask
            bool anymask = (jt * 64 + 63 > row0);
#pragma unroll
            for (int j = 0; j < 8; j++) {
                s[j][0] *= SCL; s[j][1] *= SCL;
                s[j][2] *= SCL; s[j][3] *= SCL;
                if (anymask) {
                    int c0 = jt * 64 + j * 8 + 2 * t;
                    if (c0 > row0)     s[j][0] = -1e30f;
                    if (c0 + 1 > row0) s[j][1] = -1e30f;
                    if (c0 > row1)     s[j][2] = -1e30f;
                    if (c0 + 1 > row1) s[j][3] = -1e30f;
                }
            }

            // online softmax (log2 domain)
            float mx0 = -1e30f, mx1 = -1e30f;
#pragma unroll
            for (int j = 0; j < 8; j++) {
                mx0 = fmaxf(mx0, fmaxf(s[j][0], s[j][1]));
                mx1 = fmaxf(mx1, fmaxf(s[j][2], s[j][3]));
            }
            mx0 = fmaxf(mx0, __shfl_xor_sync(0xffffffffu, mx0, 1));
            mx0 = fmaxf(mx0, __shfl_xor_sync(0xffffffffu, mx0, 2));
            mx1 = fmaxf(mx1, __shfl_xor_sync(0xffffffffu, mx1, 1));
            mx1 = fmaxf(mx1, __shfl_xor_sync(0xffffffffu, mx1, 2));
            float mn0 = fmaxf(m0, mx0), mn1 = fmaxf(m1, mx1);
            float f0 = ex2(m0 - mn0), f1 = ex2(m1 - mn1);
            float sum0 = 0.f, sum1 = 0.f;
#pragma unroll
            for (int j = 0; j < 8; j++) {
                s[j][0] = ex2(s[j][0] - mn0);
                s[j][1] = ex2(s[j][1] - mn0);
                s[j][2] = ex2(s[j][2] - mn1);
                s[j][3] = ex2(s[j][3] - mn1);
                sum0 += s[j][0] + s[j][1];
                sum1 += s[j][2] + s[j][3];
            }
            sum0 += __shfl_xor_sync(0xffffffffu, sum0, 1);
            sum0 += __shfl_xor_sync(0xffffffffu, sum0, 2);
            sum1 += __shfl_xor_sync(0xffffffffu, sum1, 1);
            sum1 += __shfl_xor_sync(0xffffffffu, sum1, 2);
            l0 = l0 * f0 + sum0; l1 = l1 * f1 + sum1;
            m0 = mn0; m1 = mn1;
#pragma unroll
            for (int jo = 0; jo < 8; jo++) {
                o[jo][0] *= f0; o[jo][1] *= f0;
                o[jo][2] *= f1; o[jo][3] *= f1;
            }

            // O += P @ V
#pragma unroll
            for (int kk = 0; kk < 4; kk++) {
                uint32_t ap[4];
                ap[0] = pkh2(s[2*kk][0],   s[2*kk][1]);
                ap[1] = pkh2(s[2*kk][2],   s[2*kk][3]);
                ap[2] = pkh2(s[2*kk+1][0], s[2*kk+1][1]);
                ap[3] = pkh2(s[2*kk+1][2], s[2*kk+1][3]);
#pragma unroll
                for (int hb = 0; hb < 4; hb++) {
                    uint32_t bv[4];
                    uint32_t a = s2u(Vs + (kk * 16 + (lane & 15)) * APITCH
                                     + hb * 16 + (lane >> 4) * 8);
                    LDSM4T(bv[0], bv[1], bv[2], bv[3], a);
                    mma_f16(o[hb * 2],     ap, bv);
                    mma_f16(o[hb * 2 + 1], ap, bv + 2);
                }
            }
        }
    }

    float inv0 = 1.f / l0, inv1 = 1.f / l1;
    __half* c0 = ctx + ((size_t)(b * TT) + row0) * DD + h * 64;
    __half* c1 = ctx + ((size_t)(b * TT) + row1) * DD + h * 64;
#pragma unroll
    for (int jo = 0; jo < 8; jo++) {
        int col = jo * 8 + 2 * t;
        *(__half2*)(c0 + col) = __floats2half2_rn(o[jo][0] * inv0, o[jo][1] * inv0);
        *(__half2*)(c1 + col) = __floats2half2_rn(o[jo][2] * inv1, o[jo][3] * inv1);
    }
}

// ---------------- launcher --------------------------------------------------
extern "C" void kernel_launch(void* const* d_in, const int* in_sizes, int n_in,
                              void* d_out, int out_size) {
    const float* x      = (const float*)d_in[0];
    const float* ln1_g  = (const float*)d_in[1];
    const float* ln1_b  = (const float*)d_in[2];
    const float* wq     = (const float*)d_in[3];
    const float* wk     = (const float*)d_in[4];
    const float* wv     = (const float*)d_in[5];
    const float* w_proj = (const float*)d_in[6];
    const float* b_proj = (const float*)d_in[7];
    const float* ln2_g  = (const float*)d_in[8];
    const float* ln2_b  = (const float*)d_in[9];
    const float* w1     = (const float*)d_in[10];
    const float* b1     = (const float*)d_in[11];
    const float* w2     = (const float*)d_in[12];
    const float* b2     = (const float*)d_in[13];
    float* out = (float*)d_out;

    __half *xn, *qkv, *ctx, *hb, *w;
    float *x1;
    cudaGetSymbolAddress((void**)&xn,  g_xn);
    cudaGetSymbolAddress((void**)&qkv, g_qkv);
    cudaGetSymbolAddress((void**)&ctx, g_ctx);
    cudaGetSymbolAddress((void**)&x1,  g_x1);
    cudaGetSymbolAddress((void**)&hb,  g_h);
    cudaGetSymbolAddress((void**)&w,   g_w);
    __half* wqkv = w;                      // [3072, 1024]
    __half* wpro = w + 3 * 1024 * 1024;    // [1024, 1024]
    __half* w1t  = w + 4 * 1024 * 1024;    // [4096, 1024]
    __half* w2t  = w + 8 * 1024 * 1024;    // [1024, 4096]

    const size_t GSMEM = (size_t)GS * STGH * sizeof(__half);          // 61440
    const size_t ASMEM = (size_t)ASMEM_HALFS * sizeof(__half);        // 55296
    cudaFuncSetAttribute(tc_gemm<true ,false,false,false>, cudaFuncAttributeMaxDynamicSharedMemorySize, GSMEM);
    cudaFuncSetAttribute(tc_gemm<false,true ,false,true >, cudaFuncAttributeMaxDynamicSharedMemorySize, GSMEM);
    cudaFuncSetAttribute(tc_gemm<true ,true ,true ,false>, cudaFuncAttributeMaxDynamicSharedMemorySize, GSMEM);
    cudaFuncSetAttribute(attn_kernel, cudaFuncAttributeMaxDynamicSharedMemorySize, ASMEM);

    dim3 tb(32, 32);
    // (1) LN1 (needs only x)
    ln_kernel<<<BT, 256>>>(x, ln1_g, ln1_b, xn);
    // (2) qkv weight repack
    transpose_qkv3<<<dim3(32, 2, 48), tb>>>(wq, wk, wv, wqkv);
    // (3) fused QKV projection: [8192, 3072] fp16 out
    tc_gemm<true,false,false,false><<<dim3(24, 64), 128, GSMEM>>>(
        xn, wqkv, nullptr, nullptr, qkv, BT, 3 * DD, DD);
    // (4) attention (fp16 mma flash, 128-row Q tiles, heavy-first)  [profiled]
    attn_kernel<<<dim3(TT / 128, BB * HH), 256, ASMEM>>>(qkv, ctx);
    // (5) proj/w1/w2 repack (single launch)
    transpose_rest<<<9216, tb>>>(w_proj, w1, w2, w);
    // (6) output projection + bias + residual -> x1 fp32
    tc_gemm<false,true,false,true><<<dim3(8, 64), 128, GSMEM>>>(
        ctx, wpro, b_proj, x, x1, BT, DD, DD);
    // (7) LN2
    ln_kernel<<<BT, 256>>>(x1, ln2_g, ln2_b, xn);
    // (8) FFN1: relu(xn @ w1 + b1) -> h fp16
    tc_gemm<true,true,true,false><<<dim3(32, 64), 128, GSMEM>>>(
        xn, w1t, b1, nullptr, hb, BT, FF, DD);
    // (9) FFN2: h @ w2 + b2 + x1 -> out fp32
    tc_gemm<false,true,false,true><<<dim3(8, 64), 128, GSMEM>>>(
        hb, w2t, b2, x1, out, BT, DD, FF);
}

// round 15
// speedup vs baseline: 1.2630x; 1.0938x over previous
#include <cuda_runtime.h>
#include <cuda_fp16.h>
#include <math.h>
#include <stdint.h>

#define BB   4
#define TT   2048
#define DD   1024
#define HH   16
#define HSV  64
#define FF   4096
#define BT   (BB*TT)
#define QLD  (3*DD)          // packed qkv row stride (halfs)

// ---------------- scratch (device globals; no runtime allocation) ----------
__device__ __half g_xn [BT*DD];
__device__ __half g_qkv[(size_t)BT*3*DD];
__device__ __half g_ctx[BT*DD];
__device__ float  g_x1 [BT*DD];
__device__ __half g_h  [(size_t)BT*FF];
__device__ __half g_w  [12*1024*1024];   // qkv' 3M | proj' 1M | w1' 4M | w2' 4M

// ---------------- small helpers --------------------------------------------
__device__ __forceinline__ uint32_t s2u(const void* p) {
    return (uint32_t)__cvta_generic_to_shared(p);
}
__device__ __forceinline__ uint32_t pkh2(float a, float b) {
    __half2 h = __floats2half2_rn(a, b);
    return *reinterpret_cast<uint32_t*>(&h);
}
__device__ __forceinline__ float ex2(float x) {
    float r;
    asm("ex2.approx.ftz.f32 %0, %1;" : "=f"(r) : "f"(x));
    return r;
}
__device__ __forceinline__ void mma_f16(float* c, const uint32_t* a, const uint32_t* b) {
    asm volatile(
        "mma.sync.aligned.m16n8k16.row.col.f32.f16.f16.f32 "
        "{%0,%1,%2,%3}, {%4,%5,%6,%7}, {%8,%9}, {%0,%1,%2,%3};"
        : "+f"(c[0]), "+f"(c[1]), "+f"(c[2]), "+f"(c[3])
        : "r"(a[0]), "r"(a[1]), "r"(a[2]), "r"(a[3]), "r"(b[0]), "r"(b[1]));
}
#define LDSM4(r0,r1,r2,r3,a) \
    asm volatile("ldmatrix.sync.aligned.m8n8.x4.shared.b16 {%0,%1,%2,%3}, [%4];" \
        : "=r"(r0),"=r"(r1),"=r"(r2),"=r"(r3) : "r"(a))
#define LDSM4T(r0,r1,r2,r3,a) \
    asm volatile("ldmatrix.sync.aligned.m8n8.x4.trans.shared.b16 {%0,%1,%2,%3}, [%4];" \
        : "=r"(r0),"=r"(r1),"=r"(r2),"=r"(r3) : "r"(a))
__device__ __forceinline__ void cpa(uint32_t dst, const void* src) {
    asm volatile("cp.async.cg.shared.global [%0], [%1], 16;"
                 :: "r"(dst), "l"(src) : "memory");
}
#define CP_COMMIT() asm volatile("cp.async.commit_group;" ::: "memory")
template<int N> __device__ __forceinline__ void cp_wait() {
    asm volatile("cp.async.wait_group %0;" :: "n"(N) : "memory");
}

// ---------------- weight repack kernels (fp32 -> fp16) ----------------------
__global__ void transpose_qkv3(const float* __restrict__ wq, const float* __restrict__ wk,
                               const float* __restrict__ wv, __half* __restrict__ out) {
    __shared__ float sm_[32][33];
    int z = blockIdx.z;
    int which = z >> 4, h = z & 15;
    const float* w = (which == 0) ? wq : (which == 1) ? wk : wv;
    __half* o = out + (size_t)which * DD * DD;
    int d0 = blockIdx.x * 32, j0 = blockIdx.y * 32;
    sm_[threadIdx.y][threadIdx.x] =
        w[((size_t)h * DD + d0 + threadIdx.y) * HSV + j0 + threadIdx.x];
    __syncthreads();
    o[(size_t)(h * HSV + j0 + threadIdx.y) * DD + d0 + threadIdx.x] =
        __float2half_rn(sm_[threadIdx.x][threadIdx.y]);
}
__global__ void transpose_rest(const float* __restrict__ wp, const float* __restrict__ w1,
                               const float* __restrict__ w2, __half* __restrict__ out) {
    __shared__ float sm_[32][33];
    int idx = blockIdx.x;
    const float* in; __half* o; int K, N, n0, k0;
    if (idx < 1024) {                        // proj: [1024,1024]
        in = wp; o = out + 3 * 1024 * 1024; K = 1024; N = 1024;
        n0 = (idx & 31) * 32; k0 = (idx >> 5) * 32;
    } else if (idx < 1024 + 4096) {          // w1: [1024,4096]
        int t = idx - 1024;
        in = w1; o = out + 4 * 1024 * 1024; K = 1024; N = 4096;
        n0 = (t & 127) * 32; k0 = (t >> 7) * 32;
    } else {                                 // w2: [4096,1024]
        int t = idx - 5120;
        in = w2; o = out + 8 * 1024 * 1024; K = 4096; N = 1024;
        n0 = (t & 31) * 32; k0 = (t >> 5) * 32;
    }
    sm_[threadIdx.y][threadIdx.x] = in[(size_t)(k0 + threadIdx.y) * N + n0 + threadIdx.x];
    __syncthreads();
    o[(size_t)(n0 + threadIdx.y) * K + k0 + threadIdx.x] =
        __float2half_rn(sm_[threadIdx.x][threadIdx.y]);
}

// ---------------- layernorm (fp32 in, fp16 out) -----------------------------
__global__ void ln_kernel(const float* __restrict__ x, const float* __restrict__ g,
                          const float* __restrict__ b, __half* __restrict__ out) {
    int row = blockIdx.x;
    const float* xr = x + (size_t)row * DD;
    float vv[4];
    float s = 0.f, sq = 0.f;
#pragma unroll
    for (int i = 0; i < 4; i++) {
        float t = xr[threadIdx.x + i * 256];
        vv[i] = t; s += t; sq += t * t;
    }
    __shared__ float red[64];
#pragma unroll
    for (int o = 16; o > 0; o >>= 1) {
        s  += __shfl_xor_sync(0xffffffffu, s, o);
        sq += __shfl_xor_sync(0xffffffffu, sq, o);
    }
    int warp = threadIdx.x >> 5, lane = threadIdx.x & 31;
    if (lane == 0) { red[warp] = s; red[warp + 8] = sq; }
    __syncthreads();
    if (threadIdx.x < 32) {
        float ss = (threadIdx.x < 8) ? red[threadIdx.x] : 0.f;
        float qq = (threadIdx.x < 8) ? red[threadIdx.x + 8] : 0.f;
#pragma unroll
        for (int o = 4; o > 0; o >>= 1) {
            ss += __shfl_xor_sync(0xffffffffu, ss, o);
            qq += __shfl_xor_sync(0xffffffffu, qq, o);
        }
        if (threadIdx.x == 0) { red[32] = ss; red[33] = qq; }
    }
    __syncthreads();
    float mean = red[32] * (1.f / DD);
    float var  = red[33] * (1.f / DD) - mean * mean;
    float inv  = rsqrtf(var + 1e-5f);
#pragma unroll
    for (int i = 0; i < 4; i++) {
        int c = threadIdx.x + i * 256;
        out[(size_t)row * DD + c] = __float2half_rn((vv[i] - mean) * inv * g[c] + b[c]);
    }
}

// ---------------- fp16 mma GEMM: C = A[MxK] @ Bt[NxK]^T ---------------------
// 128x128 CTA tile, BK=32, 3-stage cp.async, single sync/chunk
// (load-after-compute). 4 warps (2x2), warp tile 64x64, 2 CTAs/SM.
// (Round-11 validated config.)
#define GS 3
#define SPITCH 40                    // halfs per 32-col row (80B, LDSM-conflict-free)
#define STGH (2*128*SPITCH)          // halfs per stage (A+B)
#define ATILEH (128*SPITCH)

__device__ __forceinline__ void ld_stage(__half* sA, const __half* Ag, const __half* Bg,
                                         int K, int tid) {
#pragma unroll
    for (int i = 0; i < 4; i++) {
        int j = tid + (i << 7);               // 0..511 16B units (A)
        int r = j >> 2, q = j & 3;
        cpa(s2u(sA + r * SPITCH + q * 8), Ag + (size_t)r * K + q * 8);
    }
    __half* sB = sA + ATILEH;
#pragma unroll
    for (int i = 0; i < 4; i++) {
        int j = tid + (i << 7);
        int r = j >> 2, q = j & 3;
        cpa(s2u(sB + r * SPITCH + q * 8), Bg + (size_t)r * K + q * 8);
    }
}

template<bool HOUT, bool BIAS, bool RELU, bool RES>
__global__ __launch_bounds__(128, 2)
void tc_gemm(const __half* __restrict__ A, const __half* __restrict__ Bt,
             const float* __restrict__ bias, const float* __restrict__ res,
             void* __restrict__ Cv, int M, int N, int K) {
    extern __shared__ __half sm[];
    int tid = threadIdx.x, wid = tid >> 5, lane = tid & 31;
    int wm = wid >> 1, wn = wid & 1;          // warp grid 2(M) x 2(N), 64x64 tiles
    int g = lane >> 2, tig = lane & 3;
    int n0 = blockIdx.x * 128, m0 = blockIdx.y * 128;

    const __half* Ab = A + (size_t)m0 * K;
    const __half* Bb = Bt + (size_t)n0 * K;
    int nch = K >> 5;

    float acc[4][8][4] = {};                  // i(16-row) x j(8-col) x frag

    // prologue: 2 chunks in flight
#pragma unroll
    for (int c = 0; c < GS - 1; c++) {
        ld_stage(sm + c * STGH, Ab + c * 32, Bb + c * 32, K, tid);
        CP_COMMIT();
    }

    for (int c = 0; c < nch; c++) {
        cp_wait<GS - 2>();          // chunk c's load complete
        __syncthreads();            // all warps done reading buffer (c-1)%GS
        __half* sA = sm + (c % GS) * STGH;
        __half* sB = sA + ATILEH;

        uint32_t bk[8][2][2];
#pragma unroll
        for (int j = 0; j < 8; j++) {
            uint32_t a = s2u(sB + (wn * 64 + j * 8 + (lane & 7)) * SPITCH
                             + ((lane >> 3) & 3) * 8);
            LDSM4(bk[j][0][0], bk[j][0][1], bk[j][1][0], bk[j][1][1], a);
        }
#pragma unroll
        for (int kk = 0; kk < 2; kk++) {
            uint32_t af[4][4];
#pragma unroll
            for (int i = 0; i < 4; i++) {
                uint32_t a = s2u(sA + (wm * 64 + i * 16 + (lane & 15)) * SPITCH
                                 + kk * 16 + (lane >> 4) * 8);
                LDSM4(af[i][0], af[i][1], af[i][2], af[i][3], a);
            }
#pragma unroll
            for (int i = 0; i < 4; i++)
#pragma unroll
                for (int j = 0; j < 8; j++)
                    mma_f16(acc[i][j], af[i], bk[j][kk]);
        }

        // issue next load AFTER compute; target buffer (c+2)%3 held chunk c-1,
        // whose reads finished before this iteration's barrier.
        if (c + GS - 1 < nch)
            ld_stage(sm + ((c + GS - 1) % GS) * STGH,
                     Ab + (size_t)(c + GS - 1) * 32,
                     Bb + (size_t)(c + GS - 1) * 32, K, tid);
        CP_COMMIT();
    }

    // epilogue
#pragma unroll
    for (int i = 0; i < 4; i++) {
        int m_up = m0 + wm * 64 + i * 16 + g;
#pragma unroll
        for (int j = 0; j < 8; j++) {
            int n = n0 + wn * 64 + j * 8 + 2 * tig;
            float v0 = acc[i][j][0], v1 = acc[i][j][1];
            float v2 = acc[i][j][2], v3 = acc[i][j][3];
            if (BIAS) {
                float2 bv = *(const float2*)(bias + n);
                v0 += bv.x; v1 += bv.y; v2 += bv.x; v3 += bv.y;
            }
            if (RELU) {
                v0 = fmaxf(v0, 0.f); v1 = fmaxf(v1, 0.f);
                v2 = fmaxf(v2, 0.f); v3 = fmaxf(v3, 0.f);
            }
            if (RES) {
                float2 r0 = *(const float2*)(res + (size_t)m_up * N + n);
                float2 r1 = *(const float2*)(res + (size_t)(m_up + 8) * N + n);
                v0 += r0.x; v1 += r0.y; v2 += r1.x; v3 += r1.y;
            }
            if (HOUT) {
                __half* C = (__half*)Cv;
                *(__half2*)(C + (size_t)m_up * N + n) = __floats2half2_rn(v0, v1);
                *(__half2*)(C + (size_t)(m_up + 8) * N + n) = __floats2half2_rn(v2, v3);
            } else {
                float* C = (float*)Cv;
                *(float2*)(C + (size_t)m_up * N + n) = make_float2(v0, v1);
                *(float2*)(C + (size_t)(m_up + 8) * N + n) = make_float2(v2, v3);
            }
        }
    }
}

// ---------------- fp16 mma causal flash attention ---------------------------
// Q tile 128 rows (8 warps x 16), K/V tiles 64 rows double-buffered.
// Heavy-first schedule; deferred next-tile loads (after QK^T block).
// __launch_bounds__(256,2) pins regs <=128 so 2 CTAs/SM fit (round-14 fix).
#define APITCH 72
#define AQ_OFF 0
#define AK_OFF (128*APITCH)
#define AV_OFF (AK_OFF + 2*64*APITCH)
#define ASMEM_HALFS (AV_OFF + 2*64*APITCH)
#define SCL 0.18033688011112042f     // 0.125 * log2(e)

__device__ __forceinline__ void attn_ld_kv(__half* sm, int buf,
                                           const __half* kb, const __half* vb,
                                           int jt, int tid) {
    __half* Kd = sm + AK_OFF + buf * 64 * APITCH;
    __half* Vd = sm + AV_OFF + buf * 64 * APITCH;
#pragma unroll
    for (int i = 0; i < 2; i++) {
        int j = tid + (i << 8);
        int r = j >> 3, q = j & 7;
        size_t gr = (size_t)(jt * 64 + r) * QLD + q * 8;
        cpa(s2u(Kd + r * APITCH + q * 8), kb + gr);
        cpa(s2u(Vd + r * APITCH + q * 8), vb + gr);
    }
}

__global__ __launch_bounds__(256, 2)
void attn_kernel(const __half* __restrict__ qkv, __half* __restrict__ ctx) {
    extern __shared__ __half smA[];
    __half* Qs = smA + AQ_OFF;

    int qt = (int)(gridDim.x - 1 - blockIdx.x);    // heavy tiles first
    int bh = blockIdx.y;
    int b = bh >> 4, h = bh & 15;
    int tid = threadIdx.x, w = tid >> 5, lane = tid & 31;
    int g = lane >> 2, t = lane & 3;

    const __half* qb = qkv + ((size_t)(b * TT) + qt * 128) * QLD + h * 64;
    const __half* kb = qkv + (size_t)(b * TT) * QLD + DD + h * 64;
    const __half* vb = kb + DD;

    // load Q tile (128 rows x 64 cols)
#pragma unroll
    for (int i = 0; i < 4; i++) {
        int j = tid + (i << 8);
        int r = j >> 3, q = j & 7;
        cpa(s2u(Qs + r * APITCH + q * 8), qb + (size_t)r * QLD + q * 8);
    }
    CP_COMMIT();
    cp_wait<0>();
    __syncthreads();

    uint32_t qf[4][4];
#pragma unroll
    for (int kk = 0; kk < 4; kk++) {
        uint32_t a = s2u(Qs + (w * 16 + (lane & 15)) * APITCH + kk * 16 + (lane >> 4) * 8);
        LDSM4(qf[kk][0], qf[kk][1], qf[kk][2], qf[kk][3], a);
    }

    float o[8][4] = {};
    float m0 = -1e30f, m1 = -1e30f, l0 = 0.f, l1 = 0.f;
    int row0 = qt * 128 + w * 16 + g, row1 = row0 + 8;
    int wmax = qt * 128 + w * 16 + 15;      // largest q-row in this warp
    int ntiles = 2 * qt + 2;

    attn_ld_kv(smA, 0, kb, vb, 0, tid);
    CP_COMMIT();

    for (int jt = 0; jt < ntiles; jt++) {
        cp_wait<0>();
        __syncthreads();
        int cur = jt & 1;
        bool active = (jt * 64 <= wmax);
        __half* Ks = smA + AK_OFF + cur * 64 * APITCH;
        __half* Vs = smA + AV_OFF + cur * 64 * APITCH;

        // S = Q @ K^T (first compute block)
        float s[8][4] = {};
        if (active) {
#pragma unroll
            for (int j = 0; j < 8; j++) {
                uint32_t bb[4][2];
                uint32_t a0 = s2u(Ks + (j * 8 + (lane & 7)) * APITCH + ((lane >> 3) & 3) * 8);
                LDSM4(bb[0][0], bb[0][1], bb[1][0], bb[1][1], a0);
                LDSM4(bb[2][0], bb[2][1], bb[3][0], bb[3][1], a0 + 64);
#pragma unroll
                for (int kk = 0; kk < 4; kk++) mma_f16(s[j], qf[kk], bb[kk]);
            }
        }

        // issue next-tile loads AFTER the QK^T block; target buffer held jt-1,
        // whose reads finished before this iteration's barrier.
        if (jt + 1 < ntiles)
            attn_ld_kv(smA, (jt + 1) & 1, kb, vb, jt + 1, tid);
        CP_COMMIT();

        if (active) {
            // scale (log2 domain) + causal mask
            bool anymask = (jt * 64 + 63 > row0);
#pragma unroll
            for (int j = 0; j < 8; j++) {
                s[j][0] *= SCL; s[j][1] *= SCL;
                s[j][2] *= SCL; s[j][3] *= SCL;
                if (anymask) {
                    int c0 = jt * 64 + j * 8 + 2 * t;
                    if (c0 > row0)     s[j][0] = -1e30f;
                    if (c0 + 1 > row0) s[j][1] = -1e30f;
                    if (c0 > row1)     s[j][2] = -1e30f;
                    if (c0 + 1 > row1) s[j][3] = -1e30f;
                }
            }

            // online softmax (log2 domain)
            float mx0 = -1e30f, mx1 = -1e30f;
#pragma unroll
            for (int j = 0; j < 8; j++) {
                mx0 = fmaxf(mx0, fmaxf(s[j][0], s[j][1]));
                mx1 = fmaxf(mx1, fmaxf(s[j][2], s[j][3]));
            }
            mx0 = fmaxf(mx0, __shfl_xor_sync(0xffffffffu, mx0, 1));
            mx0 = fmaxf(mx0, __shfl_xor_sync(0xffffffffu, mx0, 2));
            mx1 = fmaxf(mx1, __shfl_xor_sync(0xffffffffu, mx1, 1));
            mx1 = fmaxf(mx1, __shfl_xor_sync(0xffffffffu, mx1, 2));
            float mn0 = fmaxf(m0, mx0), mn1 = fmaxf(m1, mx1);
            float f0 = ex2(m0 - mn0), f1 = ex2(m1 - mn1);
            float sum0 = 0.f, sum1 = 0.f;
#pragma unroll
            for (int j = 0; j < 8; j++) {
                s[j][0] = ex2(s[j][0] - mn0);
                s[j][1] = ex2(s[j][1] - mn0);
                s[j][2] = ex2(s[j][2] - mn1);
                s[j][3] = ex2(s[j][3] - mn1);
                sum0 += s[j][0] + s[j][1];
                sum1 += s[j][2] + s[j][3];
            }
            sum0 += __shfl_xor_sync(0xffffffffu, sum0, 1);
            sum0 += __shfl_xor_sync(0xffffffffu, sum0, 2);
            sum1 += __shfl_xor_sync(0xffffffffu, sum1, 1);
            sum1 += __shfl_xor_sync(0xffffffffu, sum1, 2);
            l0 = l0 * f0 + sum0; l1 = l1 * f1 + sum1;
            m0 = mn0; m1 = mn1;
#pragma unroll
            for (int jo = 0; jo < 8; jo++) {
                o[jo][0] *= f0; o[jo][1] *= f0;
                o[jo][2] *= f1; o[jo][3] *= f1;
            }

            // O += P @ V
#pragma unroll
            for (int kk = 0; kk < 4; kk++) {
                uint32_t ap[4];
                ap[0] = pkh2(s[2*kk][0],   s[2*kk][1]);
                ap[1] = pkh2(s[2*kk][2],   s[2*kk][3]);
                ap[2] = pkh2(s[2*kk+1][0], s[2*kk+1][1]);
                ap[3] = pkh2(s[2*kk+1][2], s[2*kk+1][3]);
#pragma unroll
                for (int hb = 0; hb < 4; hb++) {
                    uint32_t bv[4];
                    uint32_t a = s2u(Vs + (kk * 16 + (lane & 15)) * APITCH
                                     + hb * 16 + (lane >> 4) * 8);
                    LDSM4T(bv[0], bv[1], bv[2], bv[3], a);
                    mma_f16(o[hb * 2],     ap, bv);
                    mma_f16(o[hb * 2 + 1], ap, bv + 2);
                }
            }
        }
    }

    float inv0 = 1.f / l0, inv1 = 1.f / l1;
    __half* c0 = ctx + ((size_t)(b * TT) + row0) * DD + h * 64;
    __half* c1 = ctx + ((size_t)(b * TT) + row1) * DD + h * 64;
#pragma unroll
    for (int jo = 0; jo < 8; jo++) {
        int col = jo * 8 + 2 * t;
        *(__half2*)(c0 + col) = __floats2half2_rn(o[jo][0] * inv0, o[jo][1] * inv0);
        *(__half2*)(c1 + col) = __floats2half2_rn(o[jo][2] * inv1, o[jo][3] * inv1);
    }
}

// ---------------- launcher --------------------------------------------------
extern "C" void kernel_launch(void* const* d_in, const int* in_sizes, int n_in,
                              void* d_out, int out_size) {
    const float* x      = (const float*)d_in[0];
    const float* ln1_g  = (const float*)d_in[1];
    const float* ln1_b  = (const float*)d_in[2];
    const float* wq     = (const float*)d_in[3];
    const float* wk     = (const float*)d_in[4];
    const float* wv     = (const float*)d_in[5];
    const float* w_proj = (const float*)d_in[6];
    const float* b_proj = (const float*)d_in[7];
    const float* ln2_g  = (const float*)d_in[8];
    const float* ln2_b  = (const float*)d_in[9];
    const float* w1     = (const float*)d_in[10];
    const float* b1     = (const float*)d_in[11];
    const float* w2     = (const float*)d_in[12];
    const float* b2     = (const float*)d_in[13];
    float* out = (float*)d_out;

    __half *xn, *qkv, *ctx, *hb, *w;
    float *x1;
    cudaGetSymbolAddress((void**)&xn,  g_xn);
    cudaGetSymbolAddress((void**)&qkv, g_qkv);
    cudaGetSymbolAddress((void**)&ctx, g_ctx);
    cudaGetSymbolAddress((void**)&x1,  g_x1);
    cudaGetSymbolAddress((void**)&hb,  g_h);
    cudaGetSymbolAddress((void**)&w,   g_w);
    __half* wqkv = w;                      // [3072, 1024]
    __half* wpro = w + 3 * 1024 * 1024;    // [1024, 1024]
    __half* w1t  = w + 4 * 1024 * 1024;    // [4096, 1024]
    __half* w2t  = w + 8 * 1024 * 1024;    // [1024, 4096]

    const size_t GSMEM = (size_t)GS * STGH * sizeof(__half);          // 61440
    const size_t ASMEM = (size_t)ASMEM_HALFS * sizeof(__half);        // 55296
    cudaFuncSetAttribute(tc_gemm<true ,false,false,false>, cudaFuncAttributeMaxDynamicSharedMemorySize, GSMEM);
    cudaFuncSetAttribute(tc_gemm<false,true ,false,true >, cudaFuncAttributeMaxDynamicSharedMemorySize, GSMEM);
    cudaFuncSetAttribute(tc_gemm<true ,true ,true ,false>, cudaFuncAttributeMaxDynamicSharedMemorySize, GSMEM);
    cudaFuncSetAttribute(attn_kernel, cudaFuncAttributeMaxDynamicSharedMemorySize, ASMEM);

    dim3 tb(32, 32);
    // (1) LN1 (needs only x)
    ln_kernel<<<BT, 256>>>(x, ln1_g, ln1_b, xn);
    // (2) qkv weight repack
    transpose_qkv3<<<dim3(32, 2, 48), tb>>>(wq, wk, wv, wqkv);
    // (3) fused QKV projection: [8192, 3072] fp16 out
    tc_gemm<true,false,false,false><<<dim3(24, 64), 128, GSMEM>>>(
        xn, wqkv, nullptr, nullptr, qkv, BT, 3 * DD, DD);
    // (4) attention (fp16 mma flash, 128-row Q tiles, heavy-first)  [profiled]
    attn_kernel<<<dim3(TT / 128, BB * HH), 256, ASMEM>>>(qkv, ctx);
    // (5) proj/w1/w2 repack (single launch)
    transpose_rest<<<9216, tb>>>(w_proj, w1, w2, w);
    // (6) output projection + bias + residual -> x1 fp32
    tc_gemm<false,true,false,true><<<dim3(8, 64), 128, GSMEM>>>(
        ctx, wpro, b_proj, x, x1, BT, DD, DD);
    // (7) LN2
    ln_kernel<<<BT, 256>>>(x1, ln2_g, ln2_b, xn);
    // (8) FFN1: relu(xn @ w1 + b1) -> h fp16
    tc_gemm<true,true,true,false><<<dim3(32, 64), 128, GSMEM>>>(
        xn, w1t, b1, nullptr, hb, BT, FF, DD);
    // (9) FFN2: h @ w2 + b2 + x1 -> out fp32
    tc_gemm<false,true,false,true><<<dim3(8, 64), 128, GSMEM>>>(
        hb, w2t, b2, x1, out, BT, DD, FF);
}

// round 17
// speedup vs baseline: 1.2665x; 1.0028x over previous
#include <cuda_runtime.h>
#include <cuda_fp16.h>
#include <math.h>
#include <stdint.h>

#define BB   4
#define TT   2048
#define DD   1024
#define HH   16
#define HSV  64
#define FF   4096
#define BT   (BB*TT)
#define QLD  (3*DD)          // packed qkv row stride (halfs)

// ---------------- scratch (device globals; no runtime allocation) ----------
__device__ __half g_xn [BT*DD];
__device__ __half g_qkv[(size_t)BT*3*DD];
__device__ __half g_ctx[BT*DD];
__device__ float  g_x1 [BT*DD];
__device__ __half g_h  [(size_t)BT*FF];
__device__ __half g_w  [12*1024*1024];   // qkv' 3M | proj' 1M | w1' 4M | w2' 4M

// ---------------- small helpers --------------------------------------------
__device__ __forceinline__ uint32_t s2u(const void* p) {
    return (uint32_t)__cvta_generic_to_shared(p);
}
__device__ __forceinline__ uint32_t pkh2(float a, float b) {
    __half2 h = __floats2half2_rn(a, b);
    return *reinterpret_cast<uint32_t*>(&h);
}
__device__ __forceinline__ float ex2(float x) {
    float r;
    asm("ex2.approx.ftz.f32 %0, %1;" : "=f"(r) : "f"(x));
    return r;
}
__device__ __forceinline__ void mma_f16(float* c, const uint32_t* a, const uint32_t* b) {
    asm volatile(
        "mma.sync.aligned.m16n8k16.row.col.f32.f16.f16.f32 "
        "{%0,%1,%2,%3}, {%4,%5,%6,%7}, {%8,%9}, {%0,%1,%2,%3};"
        : "+f"(c[0]), "+f"(c[1]), "+f"(c[2]), "+f"(c[3])
        : "r"(a[0]), "r"(a[1]), "r"(a[2]), "r"(a[3]), "r"(b[0]), "r"(b[1]));
}
#define LDSM4(r0,r1,r2,r3,a) \
    asm volatile("ldmatrix.sync.aligned.m8n8.x4.shared.b16 {%0,%1,%2,%3}, [%4];" \
        : "=r"(r0),"=r"(r1),"=r"(r2),"=r"(r3) : "r"(a))
#define LDSM4T(r0,r1,r2,r3,a) \
    asm volatile("ldmatrix.sync.aligned.m8n8.x4.trans.shared.b16 {%0,%1,%2,%3}, [%4];" \
        : "=r"(r0),"=r"(r1),"=r"(r2),"=r"(r3) : "r"(a))
__device__ __forceinline__ void cpa(uint32_t dst, const void* src) {
    asm volatile("cp.async.cg.shared.global [%0], [%1], 16;"
                 :: "r"(dst), "l"(src) : "memory");
}
#define CP_COMMIT() asm volatile("cp.async.commit_group;" ::: "memory")
template<int N> __device__ __forceinline__ void cp_wait() {
    asm volatile("cp.async.wait_group %0;" :: "n"(N) : "memory");
}

// ---------------- weight repack kernels (fp32 -> fp16) ----------------------
__global__ void transpose_qkv3(const float* __restrict__ wq, const float* __restrict__ wk,
                               const float* __restrict__ wv, __half* __restrict__ out) {
    __shared__ float sm_[32][33];
    int z = blockIdx.z;
    int which = z >> 4, h = z & 15;
    const float* w = (which == 0) ? wq : (which == 1) ? wk : wv;
    __half* o = out + (size_t)which * DD * DD;
    int d0 = blockIdx.x * 32, j0 = blockIdx.y * 32;
    sm_[threadIdx.y][threadIdx.x] =
        w[((size_t)h * DD + d0 + threadIdx.y) * HSV + j0 + threadIdx.x];
    __syncthreads();
    o[(size_t)(h * HSV + j0 + threadIdx.y) * DD + d0 + threadIdx.x] =
        __float2half_rn(sm_[threadIdx.x][threadIdx.y]);
}
__global__ void transpose_rest(const float* __restrict__ wp, const float* __restrict__ w1,
                               const float* __restrict__ w2, __half* __restrict__ out) {
    __shared__ float sm_[32][33];
    int idx = blockIdx.x;
    const float* in; __half* o; int K, N, n0, k0;
    if (idx < 1024) {                        // proj: [1024,1024]
        in = wp; o = out + 3 * 1024 * 1024; K = 1024; N = 1024;
        n0 = (idx & 31) * 32; k0 = (idx >> 5) * 32;
    } else if (idx < 1024 + 4096) {          // w1: [1024,4096]
        int t = idx - 1024;
        in = w1; o = out + 4 * 1024 * 1024; K = 1024; N = 4096;
        n0 = (t & 127) * 32; k0 = (t >> 7) * 32;
    } else {                                 // w2: [4096,1024]
        int t = idx - 5120;
        in = w2; o = out + 8 * 1024 * 1024; K = 4096; N = 1024;
        n0 = (t & 31) * 32; k0 = (t >> 5) * 32;
    }
    sm_[threadIdx.y][threadIdx.x] = in[(size_t)(k0 + threadIdx.y) * N + n0 + threadIdx.x];
    __syncthreads();
    o[(size_t)(n0 + threadIdx.y) * K + k0 + threadIdx.x] =
        __float2half_rn(sm_[threadIdx.x][threadIdx.y]);
}

// ---------------- layernorm (fp32 in, fp16 out) -----------------------------
__global__ void ln_kernel(const float* __restrict__ x, const float* __restrict__ g,
                          const float* __restrict__ b, __half* __restrict__ out) {
    int row = blockIdx.x;
    const float* xr = x + (size_t)row * DD;
    float vv[4];
    float s = 0.f, sq = 0.f;
#pragma unroll
    for (int i = 0; i < 4; i++) {
        float t = xr[threadIdx.x + i * 256];
        vv[i] = t; s += t; sq += t * t;
    }
    __shared__ float red[64];
#pragma unroll
    for (int o = 16; o > 0; o >>= 1) {
        s  += __shfl_xor_sync(0xffffffffu, s, o);
        sq += __shfl_xor_sync(0xffffffffu, sq, o);
    }
    int warp = threadIdx.x >> 5, lane = threadIdx.x & 31;
    if (lane == 0) { red[warp] = s; red[warp + 8] = sq; }
    __syncthreads();
    if (threadIdx.x < 32) {
        float ss = (threadIdx.x < 8) ? red[threadIdx.x] : 0.f;
        float qq = (threadIdx.x < 8) ? red[threadIdx.x + 8] : 0.f;
#pragma unroll
        for (int o = 4; o > 0; o >>= 1) {
            ss += __shfl_xor_sync(0xffffffffu, ss, o);
            qq += __shfl_xor_sync(0xffffffffu, qq, o);
        }
        if (threadIdx.x == 0) { red[32] = ss; red[33] = qq; }
    }
    __syncthreads();
    float mean = red[32] * (1.f / DD);
    float var  = red[33] * (1.f / DD) - mean * mean;
    float inv  = rsqrtf(var + 1e-5f);
#pragma unroll
    for (int i = 0; i < 4; i++) {
        int c = threadIdx.x + i * 256;
        out[(size_t)row * DD + c] = __float2half_rn((vv[i] - mean) * inv * g[c] + b[c]);
    }
}

// ---------------- fp16 mma GEMM: C = A[MxK] @ Bt[NxK]^T ---------------------
// 128x128 CTA tile, BK=32, 3-stage cp.async, single sync/chunk
// (load-after-compute). 4 warps (2x2), warp tile 64x64, 2 CTAs/SM.
#define GS 3
#define SPITCH 40                    // halfs per 32-col row (80B, LDSM-conflict-free)
#define STGH (2*128*SPITCH)          // halfs per stage (A+B)
#define ATILEH (128*SPITCH)

__device__ __forceinline__ void ld_stage(__half* sA, const __half* Ag, const __half* Bg,
                                         int K, int tid) {
#pragma unroll
    for (int i = 0; i < 4; i++) {
        int j = tid + (i << 7);               // 0..511 16B units (A)
        int r = j >> 2, q = j & 3;
        cpa(s2u(sA + r * SPITCH + q * 8), Ag + (size_t)r * K + q * 8);
    }
    __half* sB = sA + ATILEH;
#pragma unroll
    for (int i = 0; i < 4; i++) {
        int j = tid + (i << 7);
        int r = j >> 2, q = j & 3;
        cpa(s2u(sB + r * SPITCH + q * 8), Bg + (size_t)r * K + q * 8);
    }
}

template<bool HOUT, bool BIAS, bool RELU, bool RES>
__global__ __launch_bounds__(128, 2)
void tc_gemm(const __half* __restrict__ A, const __half* __restrict__ Bt,
             const float* __restrict__ bias, const float* __restrict__ res,
             void* __restrict__ Cv, int M, int N, int K) {
    extern __shared__ __half sm[];
    int tid = threadIdx.x, wid = tid >> 5, lane = tid & 31;
    int wm = wid >> 1, wn = wid & 1;          // warp grid 2(M) x 2(N), 64x64 tiles
    int g = lane >> 2, tig = lane & 3;
    int n0 = blockIdx.x * 128, m0 = blockIdx.y * 128;

    const __half* Ab = A + (size_t)m0 * K;
    const __half* Bb = Bt + (size_t)n0 * K;
    int nch = K >> 5;

    float acc[4][8][4] = {};                  // i(16-row) x j(8-col) x frag

    // prologue: 2 chunks in flight
#pragma unroll
    for (int c = 0; c < GS - 1; c++) {
        ld_stage(sm + c * STGH, Ab + c * 32, Bb + c * 32, K, tid);
        CP_COMMIT();
    }

    for (int c = 0; c < nch; c++) {
        cp_wait<GS - 2>();          // chunk c's load complete
        __syncthreads();            // all warps done reading buffer (c-1)%GS
        __half* sA = sm + (c % GS) * STGH;
        __half* sB = sA + ATILEH;

        uint32_t bk[8][2][2];
#pragma unroll
        for (int j = 0; j < 8; j++) {
            uint32_t a = s2u(sB + (wn * 64 + j * 8 + (lane & 7)) * SPITCH
                             + ((lane >> 3) & 3) * 8);
            LDSM4(bk[j][0][0], bk[j][0][1], bk[j][1][0], bk[j][1][1], a);
        }
#pragma unroll
        for (int kk = 0; kk < 2; kk++) {
            uint32_t af[4][4];
#pragma unroll
            for (int i = 0; i < 4; i++) {
                uint32_t a = s2u(sA + (wm * 64 + i * 16 + (lane & 15)) * SPITCH
                                 + kk * 16 + (lane >> 4) * 8);
                LDSM4(af[i][0], af[i][1], af[i][2], af[i][3], a);
            }
#pragma unroll
            for (int i = 0; i < 4; i++)
#pragma unroll
                for (int j = 0; j < 8; j++)
                    mma_f16(acc[i][j], af[i], bk[j][kk]);
        }

        // issue next load AFTER compute; target buffer (c+2)%3 held chunk c-1,
        // whose reads finished before this iteration's barrier.
        if (c + GS - 1 < nch)
            ld_stage(sm + ((c + GS - 1) % GS) * STGH,
                     Ab + (size_t)(c + GS - 1) * 32,
                     Bb + (size_t)(c + GS - 1) * 32, K, tid);
        CP_COMMIT();
    }

    // epilogue
#pragma unroll
    for (int i = 0; i < 4; i++) {
        int m_up = m0 + wm * 64 + i * 16 + g;
#pragma unroll
        for (int j = 0; j < 8; j++) {
            int n = n0 + wn * 64 + j * 8 + 2 * tig;
            float v0 = acc[i][j][0], v1 = acc[i][j][1];
            float v2 = acc[i][j][2], v3 = acc[i][j][3];
            if (BIAS) {
                float2 bv = *(const float2*)(bias + n);
                v0 += bv.x; v1 += bv.y; v2 += bv.x; v3 += bv.y;
            }
            if (RELU) {
                v0 = fmaxf(v0, 0.f); v1 = fmaxf(v1, 0.f);
                v2 = fmaxf(v2, 0.f); v3 = fmaxf(v3, 0.f);
            }
            if (RES) {
                float2 r0 = *(const float2*)(res + (size_t)m_up * N + n);
                float2 r1 = *(const float2*)(res + (size_t)(m_up + 8) * N + n);
                v0 += r0.x; v1 += r0.y; v2 += r1.x; v3 += r1.y;
            }
            if (HOUT) {
                __half* C = (__half*)Cv;
                *(__half2*)(C + (size_t)m_up * N + n) = __floats2half2_rn(v0, v1);
                *(__half2*)(C + (size_t)(m_up + 8) * N + n) = __floats2half2_rn(v2, v3);
            } else {
                float* C = (float*)Cv;
                *(float2*)(C + (size_t)m_up * N + n) = make_float2(v0, v1);
                *(float2*)(C + (size_t)(m_up + 8) * N + n) = make_float2(v2, v3);
            }
        }
    }
}

// ---------------- fp16 mma causal flash attention ---------------------------
// Q tile 128 rows (8 warps x 16), K/V tiles 64 rows double-buffered.
// Heavy-first schedule; deferred next-tile loads; launch_bounds(256,2).
#define APITCH 72
#define AQ_OFF 0
#define AK_OFF (128*APITCH)
#define AV_OFF (AK_OFF + 2*64*APITCH)
#define ASMEM_HALFS (AV_OFF + 2*64*APITCH)
#define SCL 0.18033688011112042f     // 0.125 * log2(e)

__device__ __forceinline__ void attn_ld_kv(__half* sm, int buf,
                                           const __half* kb, const __half* vb,
                                           int jt, int tid) {
    __half* Kd = sm + AK_OFF + buf * 64 * APITCH;
    __half* Vd = sm + AV_OFF + buf * 64 * APITCH;
#pragma unroll
    for (int i = 0; i < 2; i++) {
        int j = tid + (i << 8);
        int r = j >> 3, q = j & 7;
        size_t gr = (size_t)(jt * 64 + r) * QLD + q * 8;
        cpa(s2u(Kd + r * APITCH + q * 8), kb + gr);
        cpa(s2u(Vd + r * APITCH + q * 8), vb + gr);
    }
}

__global__ __launch_bounds__(256, 2)
void attn_kernel(const __half* __restrict__ qkv, __half* __restrict__ ctx) {
    extern __shared__ __half smA[];
    __half* Qs = smA + AQ_OFF;

    int qt = (int)(gridDim.x - 1 - blockIdx.x);    // heavy tiles first
    int bh = blockIdx.y;
    int b = bh >> 4, h = bh & 15;
    int tid = threadIdx.x, w = tid >> 5, lane = tid & 31;
    int g = lane >> 2, t = lane & 3;

    const __half* qb = qkv + ((size_t)(b * TT) + qt * 128) * QLD + h * 64;
    const __half* kb = qkv + (size_t)(b * TT) * QLD + DD + h * 64;
    const __half* vb = kb + DD;

    // load Q tile (128 rows x 64 cols)
#pragma unroll
    for (int i = 0; i < 4; i++) {
        int j = tid + (i << 8);
        int r = j >> 3, q = j & 7;
        cpa(s2u(Qs + r * APITCH + q * 8), qb + (size_t)r * QLD + q * 8);
    }
    CP_COMMIT();
    cp_wait<0>();
    __syncthreads();

    uint32_t qf[4][4];
#pragma unroll
    for (int kk = 0; kk < 4; kk++) {
        uint32_t a = s2u(Qs + (w * 16 + (lane & 15)) * APITCH + kk * 16 + (lane >> 4) * 8);
        LDSM4(qf[kk][0], qf[kk][1], qf[kk][2], qf[kk][3], a);
    }

    float o[8][4] = {};
    float m0 = -1e30f, m1 = -1e30f, l0 = 0.f, l1 = 0.f;
    int row0 = qt * 128 + w * 16 + g, row1 = row0 + 8;
    int wmax = qt * 128 + w * 16 + 15;      // largest q-row in this warp
    int ntiles = 2 * qt + 2;

    attn_ld_kv(smA, 0, kb, vb, 0, tid);
    CP_COMMIT();

    for (int jt = 0; jt < ntiles; jt++) {
        cp_wait<0>();
        __syncthreads();
        int cur = jt & 1;
        bool active = (jt * 64 <= wmax);
        __half* Ks = smA + AK_OFF + cur * 64 * APITCH;
        __half* Vs = smA + AV_OFF + cur * 64 * APITCH;

        // S = Q @ K^T (first compute block)
        float s[8][4] = {};
        if (active) {
#pragma unroll
            for (int j = 0; j < 8; j++) {
                uint32_t bb[4][2];
                uint32_t a0 = s2u(Ks + (j * 8 + (lane & 7)) * APITCH + ((lane >> 3) & 3) * 8);
                LDSM4(bb[0][0], bb[0][1], bb[1][0], bb[1][1], a0);
                LDSM4(bb[2][0], bb[2][1], bb[3][0], bb[3][1], a0 + 64);
#pragma unroll
                for (int kk = 0; kk < 4; kk++) mma_f16(s[j], qf[kk], bb[kk]);
            }
        }

        // issue next-tile loads AFTER the QK^T block; target buffer held jt-1,
        // whose reads finished before this iteration's barrier.
        if (jt + 1 < ntiles)
            attn_ld_kv(smA, (jt + 1) & 1, kb, vb, jt + 1, tid);
        CP_COMMIT();

        if (active) {
            // scale (log2 domain) + causal mask
            bool anymask = (jt * 64 + 63 > row0);
#pragma unroll
            for (int j = 0; j < 8; j++) {
                s[j][0] *= SCL; s[j][1] *= SCL;
                s[j][2] *= SCL; s[j][3] *= SCL;
                if (anymask) {
                    int c0 = jt * 64 + j * 8 + 2 * t;
                    if (c0 > row0)     s[j][0] = -1e30f;
                    if (c0 + 1 > row0) s[j][1] = -1e30f;
                    if (c0 > row1)     s[j][2] = -1e30f;
                    if (c0 + 1 > row1) s[j][3] = -1e30f;
                }
            }

            // online softmax (log2 domain)
            float mx0 = -1e30f, mx1 = -1e30f;
#pragma unroll
            for (int j = 0; j < 8; j++) {
                mx0 = fmaxf(mx0, fmaxf(s[j][0], s[j][1]));
                mx1 = fmaxf(mx1, fmaxf(s[j][2], s[j][3]));
            }
            mx0 = fmaxf(mx0, __shfl_xor_sync(0xffffffffu, mx0, 1));
            mx0 = fmaxf(mx0, __shfl_xor_sync(0xffffffffu, mx0, 2));
            mx1 = fmaxf(mx1, __shfl_xor_sync(0xffffffffu, mx1, 1));
            mx1 = fmaxf(mx1, __shfl_xor_sync(0xffffffffu, mx1, 2));
            float mn0 = fmaxf(m0, mx0), mn1 = fmaxf(m1, mx1);
            float f0 = ex2(m0 - mn0), f1 = ex2(m1 - mn1);
            float sum0 = 0.f, sum1 = 0.f;
#pragma unroll
            for (int j = 0; j < 8; j++) {
                s[j][0] = ex2(s[j][0] - mn0);
                s[j][1] = ex2(s[j][1] - mn0);
                s[j][2] = ex2(s[j][2] - mn1);
                s[j][3] = ex2(s[j][3] - mn1);
                sum0 += s[j][0] + s[j][1];
                sum1 += s[j][2] + s[j][3];
            }
            sum0 += __shfl_xor_sync(0xffffffffu, sum0, 1);
            sum0 += __shfl_xor_sync(0xffffffffu, sum0, 2);
            sum1 += __shfl_xor_sync(0xffffffffu, sum1, 1);
            sum1 += __shfl_xor_sync(0xffffffffu, sum1, 2);
            l0 = l0 * f0 + sum0; l1 = l1 * f1 + sum1;
            m0 = mn0; m1 = mn1;
#pragma unroll
            for (int jo = 0; jo < 8; jo++) {
                o[jo][0] *= f0; o[jo][1] *= f0;
                o[jo][2] *= f1; o[jo][3] *= f1;
            }

            // O += P @ V
#pragma unroll
            for (int kk = 0; kk < 4; kk++) {
                uint32_t ap[4];
                ap[0] = pkh2(s[2*kk][0],   s[2*kk][1]);
                ap[1] = pkh2(s[2*kk][2],   s[2*kk][3]);
                ap[2] = pkh2(s[2*kk+1][0], s[2*kk+1][1]);
                ap[3] = pkh2(s[2*kk+1][2], s[2*kk+1][3]);
#pragma unroll
                for (int hb = 0; hb < 4; hb++) {
                    uint32_t bv[4];
                    uint32_t a = s2u(Vs + (kk * 16 + (lane & 15)) * APITCH
                                     + hb * 16 + (lane >> 4) * 8);
                    LDSM4T(bv[0], bv[1], bv[2], bv[3], a);
                    mma_f16(o[hb * 2],     ap, bv);
                    mma_f16(o[hb * 2 + 1], ap, bv + 2);
                }
            }
        }
    }

    float inv0 = 1.f / l0, inv1 = 1.f / l1;
    __half* c0 = ctx + ((size_t)(b * TT) + row0) * DD + h * 64;
    __half* c1 = ctx + ((size_t)(b * TT) + row1) * DD + h * 64;
#pragma unroll
    for (int jo = 0; jo < 8; jo++) {
        int col = jo * 8 + 2 * t;
        *(__half2*)(c0 + col) = __floats2half2_rn(o[jo][0] * inv0, o[jo][1] * inv0);
        *(__half2*)(c1 + col) = __floats2half2_rn(o[jo][2] * inv1, o[jo][3] * inv1);
    }
}

// ---------------- launcher --------------------------------------------------
extern "C" void kernel_launch(void* const* d_in, const int* in_sizes, int n_in,
                              void* d_out, int out_size) {
    const float* x      = (const float*)d_in[0];
    const float* ln1_g  = (const float*)d_in[1];
    const float* ln1_b  = (const float*)d_in[2];
    const float* wq     = (const float*)d_in[3];
    const float* wk     = (const float*)d_in[4];
    const float* wv     = (const float*)d_in[5];
    const float* w_proj = (const float*)d_in[6];
    const float* b_proj = (const float*)d_in[7];
    const float* ln2_g  = (const float*)d_in[8];
    const float* ln2_b  = (const float*)d_in[9];
    const float* w1     = (const float*)d_in[10];
    const float* b1     = (const float*)d_in[11];
    const float* w2     = (const float*)d_in[12];
    const float* b2     = (const float*)d_in[13];
    float* out = (float*)d_out;

    __half *xn, *qkv, *ctx, *hb, *w;
    float *x1;
    cudaGetSymbolAddress((void**)&xn,  g_xn);
    cudaGetSymbolAddress((void**)&qkv, g_qkv);
    cudaGetSymbolAddress((void**)&ctx, g_ctx);
    cudaGetSymbolAddress((void**)&x1,  g_x1);
    cudaGetSymbolAddress((void**)&hb,  g_h);
    cudaGetSymbolAddress((void**)&w,   g_w);
    __half* wqkv = w;                      // [3072, 1024]
    __half* wpro = w + 3 * 1024 * 1024;    // [1024, 1024]
    __half* w1t  = w + 4 * 1024 * 1024;    // [4096, 1024]
    __half* w2t  = w + 8 * 1024 * 1024;    // [1024, 4096]

    const size_t GSMEM = (size_t)GS * STGH * sizeof(__half);          // 61440
    const size_t ASMEM = (size_t)ASMEM_HALFS * sizeof(__half);        // 55296
    cudaFuncSetAttribute(tc_gemm<true ,false,false,false>, cudaFuncAttributeMaxDynamicSharedMemorySize, GSMEM);
    cudaFuncSetAttribute(tc_gemm<false,true ,false,true >, cudaFuncAttributeMaxDynamicSharedMemorySize, GSMEM);
    cudaFuncSetAttribute(tc_gemm<true ,true ,true ,false>, cudaFuncAttributeMaxDynamicSharedMemorySize, GSMEM);
    cudaFuncSetAttribute(attn_kernel, cudaFuncAttributeMaxDynamicSharedMemorySize, ASMEM);

    // Side stream + events for weight-repack overlap. Created ONCE on first
    // call and reused on every subsequent call (incl. the capture call), so
    // the per-call launch sequence is fully deterministic and no resources
    // are created while a capture is active.
    static cudaStream_t s2 = nullptr;
    static cudaEvent_t e0 = nullptr, eQ = nullptr, eR = nullptr;
    if (s2 == nullptr) {
        cudaStreamCreateWithFlags(&s2, cudaStreamNonBlocking);
        cudaEventCreateWithFlags(&e0, cudaEventDisableTiming);
        cudaEventCreateWithFlags(&eQ, cudaEventDisableTiming);
        cudaEventCreateWithFlags(&eR, cudaEventDisableTiming);
    }

    dim3 tb(32, 32);

    // fork side stream off the main (capture) stream
    cudaEventRecord(e0, 0);
    cudaStreamWaitEvent(s2, e0, 0);
    // side stream: qkv repack, then proj/w1/w2 repack
    transpose_qkv3<<<dim3(32, 2, 48), tb, 0, s2>>>(wq, wk, wv, wqkv);
    cudaEventRecord(eQ, s2);
    transpose_rest<<<9216, tb, 0, s2>>>(w_proj, w1, w2, w);
    cudaEventRecord(eR, s2);

    // main stream: LN1 (overlaps qkv repack)
    ln_kernel<<<BT, 256>>>(x, ln1_g, ln1_b, xn);
    // QKV projection needs wqkv
    cudaStreamWaitEvent(0, eQ, 0);
    tc_gemm<true,false,false,false><<<dim3(24, 64), 128, GSMEM>>>(
        xn, wqkv, nullptr, nullptr, qkv, BT, 3 * DD, DD);
    // attention (overlaps transpose_rest)
    attn_kernel<<<dim3(TT / 128, BB * HH), 256, ASMEM>>>(qkv, ctx);
    // proj needs wpro (join side stream)
    cudaStreamWaitEvent(0, eR, 0);
    tc_gemm<false,true,false,true><<<dim3(8, 64), 128, GSMEM>>>(
        ctx, wpro, b_proj, x, x1, BT, DD, DD);
    // LN2
    ln_kernel<<<BT, 256>>>(x1, ln2_g, ln2_b, xn);
    // FFN1: relu(xn @ w1 + b1) -> h fp16
    tc_gemm<true,true,true,false><<<dim3(32, 64), 128, GSMEM>>>(
        xn, w1t, b1, nullptr, hb, BT, FF, DD);
    // FFN2: h @ w2 + b2 + x1 -> out fp32
    tc_gemm<false,true,false,true><<<dim3(8, 64), 128, GSMEM>>>(
        hb, w2t, b2, x1, out, BT, DD, FF);
}